// round 6
// baseline (speedup 1.0000x reference)
#include <cuda_runtime.h>
#include <cuda_bf16.h>

// Problem constants
#define NN 16
#define CC 64
#define HH 112
#define WW 112
#define HWHW (HH*WW)               // 12544
#define TENSOR_ELEMS (NN*CC*HWHW)  // 12,845,056
#define PKW (NN*16*HWHW)           // packed words (4 channels / u32)

#define TH 16
#define TW 16

#define R_S  (10.0f/255.0f)
#define HT_S (10.0f/127.0f)

// -------- scratch (device globals; no allocation allowed) ----------
__device__ unsigned g_act1[PKW];          // u8 codes, [n][c4][h][w]
__device__ unsigned g_act2[PKW];
__device__ unsigned g_act3[PKW];
__device__ unsigned g_idq [PKW];          // s8 codes of qhtanh(identity0)
__device__ unsigned g_sgn [3*16*9*64];    // stages 1..3: packed ±1 s8, [i-1][ci4][tap][co]
__device__ float    g_w0  [64*9*64];      // stage0 ±1 floats, [ci][tap][co]
__device__ float    g_dsq [CC*CC];        // int8-quant 1x1 weights, [ci][co]
__device__ float    g_wsc [4*CC];         // binary weight per-channel scales
__device__ float    g_A   [4*CC];         // fused conv-scale * bn-inv (stage>0 includes R)
__device__ float    g_B   [4*CC];         // bn bias
__device__ float    g_bninv4 [CC];
__device__ float    g_bnbias4[CC];

// -------- f32x2 packed helpers (Blackwell FFMA2 path) ---------------
__device__ __forceinline__ unsigned long long pack_dup(float v) {
    unsigned long long r;
    asm("mov.b64 %0, {%1, %1};" : "=l"(r) : "f"(v));
    return r;
}
__device__ __forceinline__ unsigned long long fma2(unsigned long long a,
                                                   unsigned long long b,
                                                   unsigned long long c) {
    unsigned long long d;
    asm("fma.rn.f32x2 %0, %1, %2, %3;" : "=l"(d) : "l"(a), "l"(b), "l"(c));
    return d;
}
__device__ __forceinline__ void unpack2(unsigned long long v, float& lo, float& hi) {
    asm("mov.b64 {%0, %1}, %2;" : "=f"(lo), "=f"(hi) : "l"(v));
}

// -------- quantizer helpers (round-half-even matches jnp) -----------
__device__ __forceinline__ float qhtanh_f(float x) {
    float c = fminf(fmaxf(x, -10.0f), 10.0f);
    float r = rintf(__fdiv_rn(c, HT_S));
    r = fminf(fmaxf(r, -127.0f), 127.0f);
    return r * HT_S;
}
__device__ __forceinline__ float qrelu_f(float x) {
    float c = fminf(fmaxf(x, 0.0f), 10.0f);
    float r = rintf(__fdiv_rn(c, R_S));
    r = fminf(fmaxf(r, 0.0f), 255.0f);
    return r * R_S;
}
__device__ __forceinline__ unsigned qrelu_code(float x) {
    float c = fminf(fmaxf(x, 0.0f), 10.0f);
    float r = rintf(__fdiv_rn(c, R_S));
    return (unsigned)(int)fminf(r, 255.0f);
}
__device__ __forceinline__ int dp4a_us(unsigned a, unsigned b, int c) {
    int r;
    asm("dp4a.u32.s32 %0, %1, %2, %3;" : "=r"(r) : "r"(a), "r"(b), "r"(c));
    return r;
}

// -------- per-channel AVE scale for binary weights -------------------
__global__ void scale_kernel(const float* __restrict__ w, float* __restrict__ wsc) {
    int b  = blockIdx.x;          // 0..255
    const float* wc = w + b*576;
    __shared__ float red[256];
    float s = 0.f;
    for (int e = threadIdx.x; e < 576; e += 256) s += fabsf(wc[e]);
    red[threadIdx.x] = s;
    __syncthreads();
    for (int off = 128; off > 0; off >>= 1) {
        if (threadIdx.x < off) red[threadIdx.x] += red[threadIdx.x + off];
        __syncthreads();
    }
    if (threadIdx.x == 0)
        wsc[b] = fmaxf(red[0] * (1.0f/576.0f), 2e-16f);
}

// -------- sign extraction: stage0 as ±1 floats, stages 1-3 packed s8 --
__global__ void sign_kernel(const float* __restrict__ w,
                            float* __restrict__ w0, unsigned* __restrict__ sgn) {
    int t = blockIdx.x * 256 + threadIdx.x;
    if (t < 64*9*64) {            // stage0 floats [ci][tap][co]
        int co = t & 63;
        int tap = (t >> 6) % 9;
        int ci = t / 576;
        float v = w[((0*64 + co)*64 + ci)*9 + tap];
        w0[t] = (v >= 0.f) ? 1.f : -1.f;
    }
    if (t < 3*9216) {             // stages 1..3: [i-1][ci4][tap][co] packed
        int i   = t / 9216 + 1;
        int rem = t % 9216;
        int co  = rem & 63;
        int tap = (rem >> 6) % 9;
        int ci4 = rem / 576;
        unsigned word = 0;
        #pragma unroll
        for (int b = 0; b < 4; b++) {
            int ci = ci4*4 + b;
            float v = w[((i*64 + co)*64 + ci)*9 + tap];
            unsigned s = (v >= 0.f) ? 0x01u : 0xFFu;
            word |= s << (8*b);
        }
        sgn[t] = word;
    }
}

// -------- int8 narrow-range weight quant for 1x1, transposed [ci][co] -
__global__ void int8q_kernel(const float* __restrict__ w, float* __restrict__ dsq_t) {
    int co = blockIdx.x;
    const float* wc = w + co*64;
    __shared__ float red[64];
    int ci = threadIdx.x;
    red[ci] = fabsf(wc[ci]);
    __syncthreads();
    for (int off = 32; off > 0; off >>= 1) {
        if (ci < off) red[ci] = fmaxf(red[ci], red[ci + off]);
        __syncthreads();
    }
    float scale = fmaxf(red[0], 2e-16f) / 127.0f;
    float q = fminf(fmaxf(rintf(__fdiv_rn(wc[ci], scale)), -127.f), 127.f) * scale;
    dsq_t[ci*64 + co] = q;
}

// -------- fused BN / conv-scale coefficients --------------------------
__global__ void bncoef_kernel(const float* __restrict__ g, const float* __restrict__ b,
                              const float* __restrict__ m, const float* __restrict__ v,
                              const float* __restrict__ wsc,
                              float* __restrict__ A, float* __restrict__ B,
                              float* __restrict__ inv4, float* __restrict__ bias4) {
    int i = threadIdx.x;   // 320
    float iv = g[i] * __fdiv_rn(1.0f, __fsqrt_rn(v[i] + 1e-5f));
    float bias = b[i] - m[i] * iv;
    if (i < 256) {
        int s = i >> 6;
        float a = wsc[i] * iv;
        if (s > 0) a *= R_S;
        A[i] = a;
        B[i] = bias;
    } else {
        inv4[i - 256]  = iv;
        bias4[i - 256] = bias;
    }
}

// -------- 1x1 conv (downsample) + bn4 + qhtanh → packed s8 codes ------
__global__ __launch_bounds__(256, 2)
void conv1x1_kernel(const float* __restrict__ x, const float* __restrict__ wt,
                    const float* __restrict__ bninv, const float* __restrict__ bnbias,
                    unsigned* __restrict__ out) {
    int b  = blockIdx.x;          // 784 = 16 * 49
    int n  = b / 49;
    int p0 = (b - n*49) * 256;
    __shared__ float xs[16][256];
    __shared__ __align__(8) float ws[16][64];
    int t   = threadIdx.x;
    int pl  = t & 63;
    int cog = t >> 6;             // 0..3
    unsigned long long acc2[4][8];
    #pragma unroll
    for (int j = 0; j < 4; j++)
        #pragma unroll
        for (int k2 = 0; k2 < 8; k2++) acc2[j][k2] = 0ULL;

    const float* xN = x + n*CC*HWHW + p0;
    for (int c0 = 0; c0 < CC; c0 += 16) {
        __syncthreads();
        #pragma unroll
        for (int r = 0; r < 16; r++) xs[r][t] = xN[(c0 + r)*HWHW + t];
        #pragma unroll
        for (int r = 0; r < 4; r++) {
            int e = t + r*256;
            ws[e >> 6][e & 63] = wt[(c0 + (e >> 6))*64 + (e & 63)];
        }
        __syncthreads();
        #pragma unroll
        for (int ci = 0; ci < 16; ci++) {
            unsigned long long w2[8];
            #pragma unroll
            for (int k2 = 0; k2 < 8; k2++)
                w2[k2] = *(const unsigned long long*)&ws[ci][cog*16 + 2*k2];
            #pragma unroll
            for (int j = 0; j < 4; j++) {
                unsigned long long xv2 = pack_dup(xs[ci][pl + 64*j]);
                #pragma unroll
                for (int k2 = 0; k2 < 8; k2++)
                    acc2[j][k2] = fma2(xv2, w2[k2], acc2[j][k2]);
            }
        }
    }
    #pragma unroll
    for (int j = 0; j < 4; j++) {
        int pix = p0 + pl + 64*j;
        unsigned words[4] = {0,0,0,0};
        #pragma unroll
        for (int k2 = 0; k2 < 8; k2++) {
            float a0, a1;
            unpack2(acc2[j][k2], a0, a1);
            #pragma unroll
            for (int h = 0; h < 2; h++) {
                int k  = 2*k2 + h;
                int co = cog*16 + k;
                float v = fmaf(h ? a1 : a0, bninv[co], bnbias[co]);
                float c = fminf(fmaxf(v, -10.0f), 10.0f);
                float r = fminf(fmaxf(rintf(__fdiv_rn(c, HT_S)), -127.f), 127.f);
                unsigned byte = ((unsigned)(int)r) & 0xFFu;
                words[k >> 2] |= byte << (8*(k & 3));
            }
        }
        #pragma unroll
        for (int q = 0; q < 4; q++)
            out[(n*16 + cog*4 + q)*HWHW + pix] = words[q];
    }
}

// -------- stage 0: fp32 3x3 conv (±1 weights, FFMA2) + EPI0 → u8 codes
__global__ __launch_bounds__(256, 2)
void conv3x3_fp0(const float* __restrict__ in, const float* __restrict__ wq,
                 const float* __restrict__ A, const float* __restrict__ B,
                 unsigned* __restrict__ out) {
    __shared__ float in_s[8][18][20];
    __shared__ __align__(16) float w_s[8*9*64];

    int t  = threadIdx.x;
    int n  = blockIdx.z;
    int h0 = blockIdx.y * TH;
    int w0 = blockIdx.x * TW;

    int pg  = t & 31;
    int cg  = t >> 5;
    int pw  = pg & 15;
    int phb = pg >> 4;

    const float* inN = in + n*CC*HWHW;

    unsigned long long acc2[8][4];
    #pragma unroll
    for (int j = 0; j < 8; j++)
        #pragma unroll
        for (int k2 = 0; k2 < 4; k2++) acc2[j][k2] = 0ULL;

    for (int c0 = 0; c0 < CC; c0 += 8) {
        __syncthreads();
        for (int e = t; e < 8*18*18; e += 256) {
            int ci  = e / 324;
            int pos = e - ci*324;
            int r   = pos / 18;
            int c   = pos - r*18;
            int hh = h0 - 1 + r;
            int ww = w0 - 1 + c;
            float v = 0.f;
            if ((unsigned)hh < HH && (unsigned)ww < WW)
                v = inN[(c0+ci)*HWHW + hh*WW + ww];
            in_s[ci][r][c] = v;
        }
        const float* wg = wq + c0*(9*CC);
        for (int e = t; e < 8*9*CC; e += 256) w_s[e] = wg[e];
        __syncthreads();

        #pragma unroll 1
        for (int ci = 0; ci < 8; ci++) {
            #pragma unroll
            for (int dy = 0; dy < 3; dy++) {
                #pragma unroll
                for (int dx = 0; dx < 3; dx++) {
                    unsigned long long w2[4];
                    #pragma unroll
                    for (int k2 = 0; k2 < 4; k2++)
                        w2[k2] = *(const unsigned long long*)
                                 &w_s[(ci*9 + dy*3 + dx)*CC + cg*8 + 2*k2];
                    #pragma unroll
                    for (int j = 0; j < 8; j++) {
                        unsigned long long iv2 =
                            pack_dup(in_s[ci][phb + 2*j + dy][pw + dx]);
                        #pragma unroll
                        for (int k2 = 0; k2 < 4; k2++)
                            acc2[j][k2] = fma2(iv2, w2[k2], acc2[j][k2]);
                    }
                }
            }
        }
    }

    float Av[8], Bv[8];
    #pragma unroll
    for (int k = 0; k < 8; k++) { Av[k] = A[cg*8+k]; Bv[k] = B[cg*8+k]; }
    int wcol = w0 + pw;
    #pragma unroll
    for (int j = 0; j < 8; j++) {
        int h = h0 + phb + 2*j;
        int pix = h*WW + wcol;
        unsigned outw0 = 0, outw1 = 0;
        float accf[8];
        #pragma unroll
        for (int k2 = 0; k2 < 4; k2++)
            unpack2(acc2[j][k2], accf[2*k2], accf[2*k2+1]);
        #pragma unroll
        for (int k = 0; k < 8; k++) {
            int co = cg*8 + k;
            float v = fmaf(accf[k], Av[k], Bv[k]);
            float xv = in[(n*CC + co)*HWHW + pix];
            float r = qhtanh_f(v) + qhtanh_f(xv);
            unsigned code = qrelu_code(r);
            if (k < 4) outw0 |= code << (8*k);
            else       outw1 |= code << (8*(k-4));
        }
        int wbase = (n*16 + cg*2)*HWHW + pix;
        out[wbase]        = outw0;
        out[wbase + HWHW] = outw1;
    }
}

// -------- stages 1-3: exact u8×s8 dp4a conv + fused epilogue -----------
template<int EPI>
__global__ __launch_bounds__(256, 2)
void conv3x3_int(const unsigned* __restrict__ in, const unsigned* __restrict__ sgn,
                 const float* __restrict__ A, const float* __restrict__ B,
                 const unsigned* __restrict__ e1,
                 unsigned* __restrict__ outp, float* __restrict__ outf) {
    __shared__ unsigned in_s[4][18][24];         // pitch 24 → conflict-free
    __shared__ __align__(16) unsigned w_s[4*9*64];

    int t  = threadIdx.x;
    int n  = blockIdx.z;
    int h0 = blockIdx.y * TH;
    int w0 = blockIdx.x * TW;

    int pg  = t & 31;
    int cg  = t >> 5;
    int pw  = pg & 15;
    int phb = pg >> 4;

    const unsigned* inN = in + n*16*HWHW;

    int acc[8][8];
    #pragma unroll
    for (int j = 0; j < 8; j++)
        #pragma unroll
        for (int k = 0; k < 8; k++) acc[j][k] = 0;

    for (int c0 = 0; c0 < 16; c0 += 4) {
        __syncthreads();
        for (int e = t; e < 4*18*18; e += 256) {
            int l   = e / 324;
            int pos = e - l*324;
            int r   = pos / 18;
            int c   = pos - r*18;
            int hh = h0 - 1 + r;
            int ww = w0 - 1 + c;
            unsigned v = 0;
            if ((unsigned)hh < HH && (unsigned)ww < WW)
                v = inN[(c0+l)*HWHW + hh*WW + ww];
            in_s[l][r][c] = v;
        }
        const unsigned* wg = sgn + c0*576;
        for (int e = t; e < 4*9*64; e += 256) w_s[e] = wg[e];
        __syncthreads();

        #pragma unroll 1
        for (int l = 0; l < 4; l++) {
            #pragma unroll
            for (int dy = 0; dy < 3; dy++) {
                #pragma unroll
                for (int dx = 0; dx < 3; dx++) {
                    uint4 wa = *(const uint4*)&w_s[(l*9 + dy*3 + dx)*64 + cg*8];
                    uint4 wb = *(const uint4*)&w_s[(l*9 + dy*3 + dx)*64 + cg*8 + 4];
                    #pragma unroll
                    for (int j = 0; j < 8; j++) {
                        unsigned iv = in_s[l][phb + 2*j + dy][pw + dx];
                        acc[j][0] = dp4a_us(iv, wa.x, acc[j][0]);
                        acc[j][1] = dp4a_us(iv, wa.y, acc[j][1]);
                        acc[j][2] = dp4a_us(iv, wa.z, acc[j][2]);
                        acc[j][3] = dp4a_us(iv, wa.w, acc[j][3]);
                        acc[j][4] = dp4a_us(iv, wb.x, acc[j][4]);
                        acc[j][5] = dp4a_us(iv, wb.y, acc[j][5]);
                        acc[j][6] = dp4a_us(iv, wb.z, acc[j][6]);
                        acc[j][7] = dp4a_us(iv, wb.w, acc[j][7]);
                    }
                }
            }
        }
    }

    float Av[8], Bv[8];
    #pragma unroll
    for (int k = 0; k < 8; k++) { Av[k] = A[cg*8+k]; Bv[k] = B[cg*8+k]; }
    int wcol = w0 + pw;
    #pragma unroll
    for (int j = 0; j < 8; j++) {
        int h   = h0 + phb + 2*j;
        int pix = h*WW + wcol;
        int wbase = (n*16 + cg*2)*HWHW + pix;
        unsigned inw0 = in[wbase], inw1 = in[wbase + HWHW];
        unsigned e1w0 = 0, e1w1 = 0;
        if (EPI == 1 || EPI == 3) { e1w0 = e1[wbase]; e1w1 = e1[wbase + HWHW]; }
        unsigned outw0 = 0, outw1 = 0;
        #pragma unroll
        for (int k = 0; k < 8; k++) {
            float v = fmaf((float)acc[j][k], Av[k], Bv[k]);
            unsigned inw = (k < 4) ? inw0 : inw1;
            float in_val = (float)((inw >> (8*(k & 3))) & 255u) * R_S;
            float r;
            if (EPI == 0) {
                r = qhtanh_f(v) + qhtanh_f(in_val);
            } else if (EPI == 1) {
                unsigned ew = (k < 4) ? e1w0 : e1w1;
                int ec = (int)(ew << (24 - 8*(k & 3))) >> 24;   // s8 extract
                float tq = qhtanh_f(v) + (float)ec * HT_S;
                r = qhtanh_f(tq) + qhtanh_f(in_val);
            } else {  // EPI == 3
                unsigned ew = (k < 4) ? e1w0 : e1w1;
                float e_val = (float)((ew >> (8*(k & 3))) & 255u) * R_S;
                float tq = qhtanh_f(v) + qhtanh_f(e_val);
                r = qhtanh_f(in_val) + qhtanh_f(tq);
            }
            if (EPI == 3) {
                outf[(n*CC + cg*8 + k)*HWHW + pix] = qrelu_f(r);
            } else {
                unsigned code = qrelu_code(r);
                if (k < 4) outw0 |= code << (8*k);
                else       outw1 |= code << (8*(k-4));
            }
        }
        if (EPI != 3) {
            outp[wbase]        = outw0;
            outp[wbase + HWHW] = outw1;
        }
    }
}

// -------------------- host launcher --------------------------------
extern "C" void kernel_launch(void* const* d_in, const int* in_sizes, int n_in,
                              void* d_out, int out_size) {
    const float* x      = (const float*)d_in[0];
    const float* conv_w = (const float*)d_in[1];
    const float* ds_w   = (const float*)d_in[2];
    const float* bng    = (const float*)d_in[3];
    const float* bnb    = (const float*)d_in[4];
    const float* bnm    = (const float*)d_in[5];
    const float* bnvv   = (const float*)d_in[6];
    float* out = (float*)d_out;

    unsigned *act1, *act2, *act3, *idq, *sgn;
    float *w0, *dsq, *wsc, *A, *B, *inv4, *bias4;
    cudaGetSymbolAddress((void**)&act1, g_act1);
    cudaGetSymbolAddress((void**)&act2, g_act2);
    cudaGetSymbolAddress((void**)&act3, g_act3);
    cudaGetSymbolAddress((void**)&idq,  g_idq);
    cudaGetSymbolAddress((void**)&sgn,  g_sgn);
    cudaGetSymbolAddress((void**)&w0,   g_w0);
    cudaGetSymbolAddress((void**)&dsq,  g_dsq);
    cudaGetSymbolAddress((void**)&wsc,  g_wsc);
    cudaGetSymbolAddress((void**)&A,    g_A);
    cudaGetSymbolAddress((void**)&B,    g_B);
    cudaGetSymbolAddress((void**)&inv4, g_bninv4);
    cudaGetSymbolAddress((void**)&bias4,g_bnbias4);

    // weight prep
    scale_kernel<<<256, 256>>>(conv_w, wsc);
    sign_kernel<<<144, 256>>>(conv_w, w0, sgn);
    int8q_kernel<<<64, 64>>>(ds_w, dsq);
    bncoef_kernel<<<1, 320>>>(bng, bnb, bnm, bnvv, wsc, A, B, inv4, bias4);

    // downsample identity path → packed s8 codes
    conv1x1_kernel<<<784, 256>>>(x, dsq, inv4, bias4, idq);

    dim3 grid(WW/TW, HH/TH, NN);   // (7,7,16)
    // stage 0: fp32 FFMA2 conv on x → act1 (u8 codes)
    conv3x3_fp0<<<grid, 256>>>(x, w0, A + 0*CC, B + 0*CC, act1);
    // stage 1: int conv, uses identity0 (s8 codes)
    conv3x3_int<1><<<grid, 256>>>(act1, sgn + 0*9216, A + 1*CC, B + 1*CC, idq,  act2, nullptr);
    // stage 2: int conv
    conv3x3_int<0><<<grid, 256>>>(act2, sgn + 1*9216, A + 2*CC, B + 2*CC, nullptr, act3, nullptr);
    // stage 3: int conv, uses s2, writes fp32 final output
    conv3x3_int<3><<<grid, 256>>>(act3, sgn + 2*9216, A + 3*CC, B + 3*CC, act2, nullptr, out);
}

// round 10
// speedup vs baseline: 1.0475x; 1.0475x over previous
#include <cuda_runtime.h>
#include <cuda_fp16.h>

#define NN 16
#define CC 64
#define HH 112
#define WW 112
#define HWHW (HH*WW)               // 12544
#define PKW (NN*16*HWHW)           // u8-packed NHWC act words
#define XHW (NN*HWHW*32)           // f16-packed x words (hi/mid/lo)

#define R_S  (10.0f/255.0f)
#define HT_S (10.0f/127.0f)
#define SC_M (1.0f/2048.0f)        // 2^-11
#define SC_L (1.0f/4194304.0f)     // 2^-22

// -------- device scratch ----------
__device__ unsigned g_act1[PKW];
__device__ unsigned g_act2[PKW];
__device__ unsigned g_act3[PKW];
__device__ unsigned g_act4[PKW];          // stage3 u8 codes before NCHW expand
__device__ unsigned g_idq [PKW];
__device__ unsigned g_xhi [XHW];
__device__ unsigned g_xmid[XHW];
__device__ unsigned g_xlo [XHW];
__device__ __align__(16) uint2 g_bfi[3*9*2*8*32];   // int-stage B fragments
__device__ __align__(16) uint2 g_bfh[9*4*8*32];     // stage0 f16 B fragments
__device__ float    g_dsq [CC*CC];
__device__ float    g_wsc [4*CC];
__device__ float    g_A   [4*CC];
__device__ float    g_B   [4*CC];
__device__ float    g_bninv4 [CC];
__device__ float    g_bnbias4[CC];

// ================= mma wrappers =================
__device__ __forceinline__ void mma_s8(int* d, unsigned a0, unsigned a1, unsigned a2,
                                       unsigned a3, unsigned b0, unsigned b1) {
    asm volatile("mma.sync.aligned.m16n8k32.row.col.s32.u8.s8.s32 "
        "{%0,%1,%2,%3}, {%4,%5,%6,%7}, {%8,%9}, {%0,%1,%2,%3};"
        : "+r"(d[0]), "+r"(d[1]), "+r"(d[2]), "+r"(d[3])
        : "r"(a0), "r"(a1), "r"(a2), "r"(a3), "r"(b0), "r"(b1));
}
__device__ __forceinline__ void mma_f16(float* d, unsigned a0, unsigned a1, unsigned a2,
                                        unsigned a3, unsigned b0, unsigned b1) {
    asm volatile("mma.sync.aligned.m16n8k16.row.col.f32.f16.f16.f32 "
        "{%0,%1,%2,%3}, {%4,%5,%6,%7}, {%8,%9}, {%0,%1,%2,%3};"
        : "+f"(d[0]), "+f"(d[1]), "+f"(d[2]), "+f"(d[3])
        : "r"(a0), "r"(a1), "r"(a2), "r"(a3), "r"(b0), "r"(b1));
}

// ================= quantizers (round-half-even, match jnp) =================
__device__ __forceinline__ float qhtanh_f(float x) {
    float c = fminf(fmaxf(x, -10.0f), 10.0f);
    float r = rintf(__fdiv_rn(c, HT_S));
    r = fminf(fmaxf(r, -127.0f), 127.0f);
    return r * HT_S;
}
__device__ __forceinline__ unsigned qrelu_code(float x) {
    float c = fminf(fmaxf(x, 0.0f), 10.0f);
    float r = rintf(__fdiv_rn(c, R_S));
    return (unsigned)(int)fminf(r, 255.0f);
}
__device__ __forceinline__ unsigned long long pack_dup(float v) {
    unsigned long long r;
    asm("mov.b64 %0, {%1, %1};" : "=l"(r) : "f"(v));
    return r;
}
__device__ __forceinline__ unsigned long long fma2(unsigned long long a, unsigned long long b,
                                                   unsigned long long c) {
    unsigned long long d;
    asm("fma.rn.f32x2 %0, %1, %2, %3;" : "=l"(d) : "l"(a), "l"(b), "l"(c));
    return d;
}
__device__ __forceinline__ void unpack2(unsigned long long v, float& lo, float& hi) {
    asm("mov.b64 {%0, %1}, %2;" : "=f"(lo), "=f"(hi) : "l"(v));
}

// ================= prep kernels =================
__global__ void scale_kernel(const float* __restrict__ w, float* __restrict__ wsc) {
    int b = blockIdx.x;                  // 0..255
    const float* wc = w + b*576;
    __shared__ float red[256];
    float s = 0.f;
    for (int e = threadIdx.x; e < 576; e += 256) s += fabsf(wc[e]);
    red[threadIdx.x] = s;
    __syncthreads();
    for (int off = 128; off > 0; off >>= 1) {
        if (threadIdx.x < off) red[threadIdx.x] += red[threadIdx.x+off];
        __syncthreads();
    }
    if (threadIdx.x == 0) wsc[b] = fmaxf(red[0] * (1.0f/576.0f), 2e-16f);
}

// B fragments for int stages: [s][tap][c][nt][lane] -> (b0,b1)
__global__ void bfrag_i_kernel(const float* __restrict__ w, uint2* __restrict__ bf) {
    int idx = blockIdx.x*256 + threadIdx.x;
    if (idx >= 3*9*2*8*32) return;
    int lane = idx & 31;
    int nt   = (idx >> 5) & 7;
    int c    = (idx >> 8) & 1;
    int tap  = (idx >> 9) % 9;
    int s    = idx / 4608;
    int co   = nt*8 + (lane >> 2);
    unsigned b0 = 0, b1 = 0;
    #pragma unroll
    for (int j = 0; j < 4; j++) {
        int ci0 = c*32 + (lane & 3)*4 + j;
        float v0 = w[(((s+1)*64 + co)*64 + ci0)*9 + tap];
        float v1 = w[(((s+1)*64 + co)*64 + ci0 + 16)*9 + tap];
        b0 |= ((v0 >= 0.f) ? 0x01u : 0xFFu) << (8*j);
        b1 |= ((v1 >= 0.f) ? 0x01u : 0xFFu) << (8*j);
    }
    bf[idx] = make_uint2(b0, b1);
}

// B fragments for stage0 f16: [tap][c][nt][lane] -> (b0,b1)
__global__ void bfrag_h_kernel(const float* __restrict__ w, uint2* __restrict__ bf) {
    int idx = blockIdx.x*256 + threadIdx.x;
    if (idx >= 9*4*8*32) return;
    int lane = idx & 31;
    int nt   = (idx >> 5) & 7;
    int c    = (idx >> 8) & 3;
    int tap  = idx >> 10;
    int co   = nt*8 + (lane >> 2);
    int ci   = c*16 + (lane & 3)*2;
    unsigned h00 = (w[((0*64+co)*64 + ci  )*9 + tap] >= 0.f) ? 0x3C00u : 0xBC00u;
    unsigned h01 = (w[((0*64+co)*64 + ci+1)*9 + tap] >= 0.f) ? 0x3C00u : 0xBC00u;
    unsigned h10 = (w[((0*64+co)*64 + ci+8)*9 + tap] >= 0.f) ? 0x3C00u : 0xBC00u;
    unsigned h11 = (w[((0*64+co)*64 + ci+9)*9 + tap] >= 0.f) ? 0x3C00u : 0xBC00u;
    bf[idx] = make_uint2(h00 | (h01 << 16), h10 | (h11 << 16));
}

__global__ void int8q_kernel(const float* __restrict__ w, float* __restrict__ dsq_t) {
    int co = blockIdx.x;
    const float* wc = w + co*64;
    __shared__ float red[64];
    int ci = threadIdx.x;
    red[ci] = fabsf(wc[ci]);
    __syncthreads();
    for (int off = 32; off > 0; off >>= 1) {
        if (ci < off) red[ci] = fmaxf(red[ci], red[ci+off]);
        __syncthreads();
    }
    float scale = fmaxf(red[0], 2e-16f) / 127.0f;
    float q = fminf(fmaxf(rintf(__fdiv_rn(wc[ci], scale)), -127.f), 127.f) * scale;
    dsq_t[ci*64 + co] = q;
}

__global__ void bncoef_kernel(const float* __restrict__ g, const float* __restrict__ b,
                              const float* __restrict__ m, const float* __restrict__ v,
                              const float* __restrict__ wsc,
                              float* __restrict__ A, float* __restrict__ B,
                              float* __restrict__ inv4, float* __restrict__ bias4) {
    int i = threadIdx.x;   // 320
    float iv = g[i] * __fdiv_rn(1.0f, __fsqrt_rn(v[i] + 1e-5f));
    float bias = b[i] - m[i] * iv;
    if (i < 256) {
        int s = i >> 6;
        float a = wsc[i] * iv;
        if (s > 0) a *= R_S;
        A[i] = a;
        B[i] = bias;
    } else {
        inv4[i-256] = iv;
        bias4[i-256] = bias;
    }
}

// x NCHW fp32 -> NHWC f16 hi/mid/lo; SCALED split (all terms f16-normal):
//   hi  = f16(x)
//   mid = f16(r1 * 2^11),  r1 = x - hi
//   lo  = f16(r2 * 2^22),  r2 = r1 - mid*2^-11
// Reconstruction (hi + mid*2^-11) + lo*2^-22 == x exactly (residual <= 2^-33|x|).
__global__ void transpose_kernel(const float* __restrict__ x,
                                 unsigned* __restrict__ xhi,
                                 unsigned* __restrict__ xmid,
                                 unsigned* __restrict__ xlo) {
    __shared__ unsigned short shi[64][66], smd[64][66], slo[64][66];
    int blk = blockIdx.x;                    // 16*196
    int n = blk / 196;
    int pix0 = (blk % 196) * 64;
    int tid = threadIdx.x;
    #pragma unroll
    for (int pass = 0; pass < 16; pass++) {
        int idx = tid + pass*256;
        int c = idx >> 6, p = idx & 63;
        float v = x[((size_t)n*64 + c)*HWHW + pix0 + p];
        __half h = __float2half_rn(v);
        float r1 = v - __half2float(h);
        __half m = __float2half_rn(r1 * 2048.0f);
        float r2 = r1 - __half2float(m) * SC_M;
        __half l = __float2half_rn(r2 * 4194304.0f);
        shi[p][c] = __half_as_ushort(h);
        smd[p][c] = __half_as_ushort(m);
        slo[p][c] = __half_as_ushort(l);
    }
    __syncthreads();
    int px = tid >> 2, part = tid & 3;
    size_t base = ((size_t)n*HWHW + pix0 + px)*32 + part*8;
    #pragma unroll
    for (int i = 0; i < 8; i++) {
        int c = part*16 + i*2;
        xhi [base+i] = (unsigned)shi[px][c] | ((unsigned)shi[px][c+1] << 16);
        xmid[base+i] = (unsigned)smd[px][c] | ((unsigned)smd[px][c+1] << 16);
        xlo [base+i] = (unsigned)slo[px][c] | ((unsigned)slo[px][c+1] << 16);
    }
}

// -------- 1x1 conv (downsample) + bn4 + qhtanh -> NHWC packed s8 ------
__global__ __launch_bounds__(256, 2)
void conv1x1_kernel(const float* __restrict__ x, const float* __restrict__ wt,
                    const float* __restrict__ bninv, const float* __restrict__ bnbias,
                    unsigned* __restrict__ out) {
    int b  = blockIdx.x;          // 784 = 16 * 49
    int n  = b / 49;
    int p0 = (b - n*49) * 256;
    __shared__ float xs[16][256];
    __shared__ __align__(8) float ws[16][64];
    __shared__ unsigned s_out[256][16];
    int t   = threadIdx.x;
    int pl  = t & 63;
    int cog = t >> 6;
    unsigned long long acc2[4][8];
    #pragma unroll
    for (int j = 0; j < 4; j++)
        #pragma unroll
        for (int k2 = 0; k2 < 8; k2++) acc2[j][k2] = 0ULL;

    const float* xN = x + (size_t)n*CC*HWHW + p0;
    for (int c0 = 0; c0 < CC; c0 += 16) {
        __syncthreads();
        #pragma unroll
        for (int r = 0; r < 16; r++) xs[r][t] = xN[(size_t)(c0+r)*HWHW + t];
        #pragma unroll
        for (int r = 0; r < 4; r++) {
            int e = t + r*256;
            ws[e>>6][e&63] = wt[(c0 + (e>>6))*64 + (e&63)];
        }
        __syncthreads();
        #pragma unroll
        for (int ci = 0; ci < 16; ci++) {
            unsigned long long w2[8];
            #pragma unroll
            for (int k2 = 0; k2 < 8; k2++)
                w2[k2] = *(const unsigned long long*)&ws[ci][cog*16 + 2*k2];
            #pragma unroll
            for (int j = 0; j < 4; j++) {
                unsigned long long xv2 = pack_dup(xs[ci][pl + 64*j]);
                #pragma unroll
                for (int k2 = 0; k2 < 8; k2++)
                    acc2[j][k2] = fma2(xv2, w2[k2], acc2[j][k2]);
            }
        }
    }
    #pragma unroll
    for (int j = 0; j < 4; j++) {
        unsigned words[4] = {0,0,0,0};
        #pragma unroll
        for (int k2 = 0; k2 < 8; k2++) {
            float a0, a1;
            unpack2(acc2[j][k2], a0, a1);
            #pragma unroll
            for (int h = 0; h < 2; h++) {
                int k = 2*k2 + h;
                int co = cog*16 + k;
                float v = fmaf(h ? a1 : a0, bninv[co], bnbias[co]);
                float c = fminf(fmaxf(v, -10.0f), 10.0f);
                float r = fminf(fmaxf(rintf(__fdiv_rn(c, HT_S)), -127.f), 127.f);
                words[k>>2] |= (((unsigned)(int)r) & 0xFFu) << (8*(k&3));
            }
        }
        #pragma unroll
        for (int q = 0; q < 4; q++) s_out[pl + 64*j][cog*4 + q] = words[q];
    }
    __syncthreads();
    uint4* gdst = (uint4*)(out + ((size_t)n*HWHW + p0 + t)*16);
    const uint4* srow = (const uint4*)&s_out[t][0];
    #pragma unroll
    for (int q = 0; q < 4; q++) gdst[q] = srow[q];
}

// ================ IMMA int stages (EPI 0/1/3) ================
// smem: sB uint2[4608] (36864B) | halo u32[10*18 px][17] (12240B, reused as staging)
#define HPITCH_I 17
template<int EPI>
__global__ __launch_bounds__(256, 2)
void conv3x3_imma(const unsigned* __restrict__ act_in, const uint2* __restrict__ bfrag,
                  const float* __restrict__ Acoef, const float* __restrict__ Bcoef,
                  const unsigned* __restrict__ e1, unsigned* __restrict__ outp) {
    extern __shared__ char dsm[];
    uint2* sBf = (uint2*)dsm;
    unsigned* halo = (unsigned*)(dsm + 36864);
    __shared__ float sAc[64], sBc[64];

    int tid = threadIdx.x;
    int wid = tid >> 5;
    int lane = tid & 31;
    int n  = blockIdx.z;
    int h0 = blockIdx.y * 8;
    int w0 = blockIdx.x * 16;

    if (tid < 64) { sAc[tid] = Acoef[tid]; sBc[tid] = Bcoef[tid]; }
    {
        const uint4* src = (const uint4*)bfrag;
        uint4* dst = (uint4*)sBf;
        #pragma unroll
        for (int i = 0; i < 9; i++) dst[tid + i*256] = src[tid + i*256];
    }
    const unsigned* inN = act_in + (size_t)n*HWHW*16;
    for (int e = tid; e < 2880; e += 256) {
        int r = e / 288, rr = e % 288, c = rr >> 4, q = rr & 15;
        int hh = h0 - 1 + r, ww = w0 - 1 + c;
        unsigned v = 0;
        if ((unsigned)hh < HH && (unsigned)ww < WW)
            v = inN[((size_t)hh*WW + ww)*16 + q];
        halo[(r*18 + c)*HPITCH_I + q] = v;
    }
    __syncthreads();

    int acc[8][4];
    #pragma unroll
    for (int nt = 0; nt < 8; nt++)
        #pragma unroll
        for (int q = 0; q < 4; q++) acc[nt][q] = 0;

    #pragma unroll 1
    for (int dy = 0; dy < 3; dy++)
    #pragma unroll
    for (int dx = 0; dx < 3; dx++) {
        int rbase = ((wid + dy)*18 + (lane >> 2) + dx)*HPITCH_I;
        #pragma unroll
        for (int c = 0; c < 2; c++) {
            unsigned a0 = halo[rbase + c*8 + (lane & 3)];
            unsigned a2 = halo[rbase + c*8 + 4 + (lane & 3)];
            unsigned a1 = halo[rbase + 8*HPITCH_I + c*8 + (lane & 3)];
            unsigned a3 = halo[rbase + 8*HPITCH_I + c*8 + 4 + (lane & 3)];
            const uint2* bp = sBf + ((dy*3 + dx)*2 + c)*256 + lane;
            #pragma unroll
            for (int nt = 0; nt < 8; nt++) {
                uint2 b = bp[nt*32];
                mma_s8(acc[nt], a0, a1, a2, a3, b.x, b.y);
            }
        }
    }

    // epilogue -> u8 code pairs
    unsigned short pairs[2][8];
    int ctr_row = (wid + 1)*18;
    #pragma unroll
    for (int h2 = 0; h2 < 2; h2++) {
        int px = (lane >> 2) + 8*h2;
        int ctr = (ctr_row + px + 1)*HPITCH_I;
        size_t pixw = ((size_t)n*HWHW + (size_t)(h0 + wid)*WW + (w0 + px))*16;
        int wsel = (lane & 3) >> 1;
        int b0 = ((lane & 3) & 1)*2;
        #pragma unroll
        for (int nt = 0; nt < 8; nt++) {
            unsigned inw = halo[ctr + 2*nt + wsel];
            unsigned ew = 0;
            if (EPI == 1 || EPI == 3) ew = e1[pixw + 2*nt + wsel];
            unsigned pr = 0;
            #pragma unroll
            for (int j = 0; j < 2; j++) {
                int co = nt*8 + (lane & 3)*2 + j;
                float v = fmaf((float)acc[nt][2*h2 + j], sAc[co], sBc[co]);
                int byte = b0 + j;
                float in_val = (float)((inw >> (8*byte)) & 255u) * R_S;
                float r;
                if (EPI == 0) {
                    r = qhtanh_f(v) + qhtanh_f(in_val);
                } else if (EPI == 1) {
                    int ec = (int)(ew << (24 - 8*byte)) >> 24;
                    float tq = qhtanh_f(v) + (float)ec * HT_S;
                    r = qhtanh_f(tq) + qhtanh_f(in_val);
                } else {
                    float ev = (float)((ew >> (8*byte)) & 255u) * R_S;
                    float tq = qhtanh_f(v) + qhtanh_f(ev);
                    r = qhtanh_f(in_val) + qhtanh_f(tq);
                }
                pr |= qrelu_code(r) << (8*j);
            }
            pairs[h2][nt] = (unsigned short)pr;
        }
    }
    __syncthreads();                       // all halo reads done; reuse as staging
    unsigned short* stag = (unsigned short*)halo;
    #pragma unroll
    for (int h2 = 0; h2 < 2; h2++) {
        int px = (lane >> 2) + 8*h2;
        int pxl = wid*16 + px;
        #pragma unroll
        for (int nt = 0; nt < 8; nt++)
            stag[pxl*32 + nt*4 + (lane & 3)] = pairs[h2][nt];
    }
    __syncthreads();
    {
        int pxl = tid >> 1, half = tid & 1;
        int h = h0 + (pxl >> 4), w = w0 + (pxl & 15);
        const uint4* src = (const uint4*)((char*)halo + pxl*64 + half*32);
        uint4* dst = (uint4*)(outp + ((size_t)n*HWHW + (size_t)h*WW + w)*16 + half*8);
        dst[0] = src[0];
        dst[1] = src[1];
    }
}

// ================ HMMA stage 0 (fp32 via scaled f16 hi/mid/lo) ================
// smem: sB uint2[9216] (73728B) | 3 halos u32[180][34] (24480B each)
#define HPITCH_H 34
__global__ __launch_bounds__(256, 1)
void conv3x3_hmma0(const unsigned* __restrict__ xhi, const unsigned* __restrict__ xmid,
                   const unsigned* __restrict__ xlo,
                   const uint2* __restrict__ bfrag,
                   const float* __restrict__ Acoef, const float* __restrict__ Bcoef,
                   unsigned* __restrict__ outp) {
    extern __shared__ char dsm[];
    uint2* sBf = (uint2*)dsm;
    unsigned* haloHi  = (unsigned*)(dsm + 73728);
    unsigned* haloMid = (unsigned*)(dsm + 73728 + 24480);
    unsigned* haloLo  = (unsigned*)(dsm + 73728 + 2*24480);
    __shared__ float sAc[64], sBc[64];

    int tid = threadIdx.x;
    int wid = tid >> 5;
    int lane = tid & 31;
    int n  = blockIdx.z;
    int h0 = blockIdx.y * 8;
    int w0 = blockIdx.x * 16;

    if (tid < 64) { sAc[tid] = Acoef[tid]; sBc[tid] = Bcoef[tid]; }
    {
        const uint4* src = (const uint4*)bfrag;
        uint4* dst = (uint4*)sBf;
        #pragma unroll
        for (int i = 0; i < 18; i++) dst[tid + i*256] = src[tid + i*256];
    }
    for (int e = tid; e < 5760; e += 256) {
        int r = e / 576, rr = e % 576, c = rr >> 5, q = rr & 31;
        int hh = h0 - 1 + r, ww = w0 - 1 + c;
        unsigned vh = 0, vm = 0, vl = 0;
        if ((unsigned)hh < HH && (unsigned)ww < WW) {
            size_t gw = ((size_t)n*HWHW + (size_t)hh*WW + ww)*32 + q;
            vh = xhi[gw]; vm = xmid[gw]; vl = xlo[gw];
        }
        haloHi [(r*18 + c)*HPITCH_H + q] = vh;
        haloMid[(r*18 + c)*HPITCH_H + q] = vm;
        haloLo [(r*18 + c)*HPITCH_H + q] = vl;
    }
    __syncthreads();

    // three accumulator sets: hi / mid / lo passes
    float acc[3][8][4];
    #pragma unroll
    for (int p = 0; p < 3; p++)
        #pragma unroll
        for (int nt = 0; nt < 8; nt++)
            #pragma unroll
            for (int q = 0; q < 4; q++) acc[p][nt][q] = 0.f;

    #pragma unroll 1
    for (int pass = 0; pass < 3; pass++) {
        const unsigned* hal = (pass == 0) ? haloHi : (pass == 1) ? haloMid : haloLo;
        #pragma unroll 1
        for (int dy = 0; dy < 3; dy++)
        #pragma unroll
        for (int dx = 0; dx < 3; dx++) {
            int rbase = ((wid + dy)*18 + (lane >> 2) + dx)*HPITCH_H;
            #pragma unroll
            for (int c = 0; c < 4; c++) {
                unsigned a0 = hal[rbase + c*8 + (lane & 3)];
                unsigned a2 = hal[rbase + c*8 + 4 + (lane & 3)];
                unsigned a1 = hal[rbase + 8*HPITCH_H + c*8 + (lane & 3)];
                unsigned a3 = hal[rbase + 8*HPITCH_H + c*8 + 4 + (lane & 3)];
                const uint2* bp = sBf + ((dy*3 + dx)*4 + c)*256 + lane;
                #pragma unroll
                for (int nt = 0; nt < 8; nt++) {
                    uint2 b = bp[nt*32];
                    mma_f16(acc[pass][nt], a0, a1, a2, a3, b.x, b.y);
                }
            }
        }
    }

    // epilogue: D = Dhi + Dmid*2^-11 + Dlo*2^-22;  x = (hi + mid*2^-11) + lo*2^-22 (exact)
    unsigned short pairs[2][8];
    int ctr_row = (wid + 1)*18;
    #pragma unroll
    for (int h2 = 0; h2 < 2; h2++) {
        int px = (lane >> 2) + 8*h2;
        int ctr = (ctr_row + px + 1)*HPITCH_H;
        #pragma unroll
        for (int nt = 0; nt < 8; nt++) {
            unsigned wh = haloHi [ctr + nt*4 + (lane & 3)];
            unsigned wm = haloMid[ctr + nt*4 + (lane & 3)];
            unsigned wl = haloLo [ctr + nt*4 + (lane & 3)];
            unsigned pr = 0;
            #pragma unroll
            for (int j = 0; j < 2; j++) {
                int co = nt*8 + (lane & 3)*2 + j;
                float D = acc[0][nt][2*h2 + j]
                        + acc[1][nt][2*h2 + j] * SC_M
                        + acc[2][nt][2*h2 + j] * SC_L;
                float v = fmaf(D, sAc[co], sBc[co]);
                __half xh = __ushort_as_half((unsigned short)((wh >> (16*j)) & 0xFFFF));
                __half xm = __ushort_as_half((unsigned short)((wm >> (16*j)) & 0xFFFF));
                __half xl = __ushort_as_half((unsigned short)((wl >> (16*j)) & 0xFFFF));
                float xv = (__half2float(xh) + __half2float(xm) * SC_M)
                         + __half2float(xl) * SC_L;
                float r = qhtanh_f(v) + qhtanh_f(xv);
                pr |= qrelu_code(r) << (8*j);
            }
            pairs[h2][nt] = (unsigned short)pr;
        }
    }
    __syncthreads();
    unsigned short* stag = (unsigned short*)haloHi;
    #pragma unroll
    for (int h2 = 0; h2 < 2; h2++) {
        int px = (lane >> 2) + 8*h2;
        int pxl = wid*16 + px;
        #pragma unroll
        for (int nt = 0; nt < 8; nt++)
            stag[pxl*32 + nt*4 + (lane & 3)] = pairs[h2][nt];
    }
    __syncthreads();
    {
        int pxl = tid >> 1, half = tid & 1;
        int h = h0 + (pxl >> 4), w = w0 + (pxl & 15);
        const uint4* src = (const uint4*)((char*)haloHi + pxl*64 + half*32);
        uint4* dst = (uint4*)(outp + ((size_t)n*HWHW + (size_t)h*WW + w)*16 + half*8);
        dst[0] = src[0];
        dst[1] = src[1];
    }
}

// -------- final: u8 NHWC codes -> fp32 NCHW (out = code * R_S) --------
__global__ void out_expand_kernel(const unsigned* __restrict__ codes,
                                  float* __restrict__ out) {
    __shared__ unsigned st[64][17];
    int blk = blockIdx.x;             // 16*196
    int n = blk / 196;
    int pix0 = (blk % 196) * 64;
    int tid = threadIdx.x;
    #pragma unroll
    for (int i = 0; i < 4; i++) {
        int e = tid + i*256;
        int px = e >> 4, q = e & 15;
        st[px][q] = codes[((size_t)n*HWHW + pix0 + px)*16 + q];
    }
    __syncthreads();
    int c = tid >> 2, qq = tid & 3;
    float* dst = out + ((size_t)n*64 + c)*HWHW + pix0 + qq*16;
    #pragma unroll
    for (int i = 0; i < 16; i++) {
        unsigned w = st[qq*16 + i][c >> 2];
        dst[i] = (float)((w >> (8*(c & 3))) & 255u) * R_S;
    }
}

// -------------------- host launcher --------------------------------
extern "C" void kernel_launch(void* const* d_in, const int* in_sizes, int n_in,
                              void* d_out, int out_size) {
    const float* x      = (const float*)d_in[0];
    const float* conv_w = (const float*)d_in[1];
    const float* ds_w   = (const float*)d_in[2];
    const float* bng    = (const float*)d_in[3];
    const float* bnb    = (const float*)d_in[4];
    const float* bnm    = (const float*)d_in[5];
    const float* bnvv   = (const float*)d_in[6];
    float* out = (float*)d_out;

    unsigned *act1, *act2, *act3, *act4, *idq, *xhi, *xmid, *xlo;
    uint2 *bfi, *bfh;
    float *dsq, *wsc, *A, *B, *inv4, *bias4;
    cudaGetSymbolAddress((void**)&act1, g_act1);
    cudaGetSymbolAddress((void**)&act2, g_act2);
    cudaGetSymbolAddress((void**)&act3, g_act3);
    cudaGetSymbolAddress((void**)&act4, g_act4);
    cudaGetSymbolAddress((void**)&idq,  g_idq);
    cudaGetSymbolAddress((void**)&xhi,  g_xhi);
    cudaGetSymbolAddress((void**)&xmid, g_xmid);
    cudaGetSymbolAddress((void**)&xlo,  g_xlo);
    cudaGetSymbolAddress((void**)&bfi,  g_bfi);
    cudaGetSymbolAddress((void**)&bfh,  g_bfh);
    cudaGetSymbolAddress((void**)&dsq,  g_dsq);
    cudaGetSymbolAddress((void**)&wsc,  g_wsc);
    cudaGetSymbolAddress((void**)&A,    g_A);
    cudaGetSymbolAddress((void**)&B,    g_B);
    cudaGetSymbolAddress((void**)&inv4, g_bninv4);
    cudaGetSymbolAddress((void**)&bias4,g_bnbias4);

    const int SMEMI = 36864 + 12240;            // 49,104
    const int SMEM0 = 73728 + 3*24480;          // 147,168
    cudaFuncSetAttribute(conv3x3_hmma0,   cudaFuncAttributeMaxDynamicSharedMemorySize, SMEM0);
    cudaFuncSetAttribute(conv3x3_imma<0>, cudaFuncAttributeMaxDynamicSharedMemorySize, SMEMI);
    cudaFuncSetAttribute(conv3x3_imma<1>, cudaFuncAttributeMaxDynamicSharedMemorySize, SMEMI);
    cudaFuncSetAttribute(conv3x3_imma<3>, cudaFuncAttributeMaxDynamicSharedMemorySize, SMEMI);

    // prep
    scale_kernel<<<256, 256>>>(conv_w, wsc);
    bfrag_i_kernel<<<(3*9*2*8*32 + 255)/256, 256>>>(conv_w, bfi);
    bfrag_h_kernel<<<(9*4*8*32 + 255)/256, 256>>>(conv_w, bfh);
    int8q_kernel<<<64, 64>>>(ds_w, dsq);
    bncoef_kernel<<<1, 320>>>(bng, bnb, bnm, bnvv, wsc, A, B, inv4, bias4);
    transpose_kernel<<<16*196, 256>>>(x, xhi, xmid, xlo);

    // downsample identity path -> NHWC s8 codes
    conv1x1_kernel<<<784, 256>>>(x, dsq, inv4, bias4, idq);

    dim3 grid(7, 14, NN);   // 16w x 8h tiles
    // stage 0: HMMA scaled hi/mid/lo conv on x -> act1 (NHWC u8)
    conv3x3_hmma0<<<grid, 256, SMEM0>>>(xhi, xmid, xlo, bfh, A + 0*CC, B + 0*CC, act1);
    // stage 1 (EPI1, e1 = idq s8)
    conv3x3_imma<1><<<grid, 256, SMEMI>>>(act1, bfi + 0*4608, A + 1*CC, B + 1*CC, idq,  act2);
    // stage 2 (EPI0)
    conv3x3_imma<0><<<grid, 256, SMEMI>>>(act2, bfi + 1*4608, A + 2*CC, B + 2*CC, nullptr, act3);
    // stage 3 (EPI3, e1 = act2) -> u8 codes
    conv3x3_imma<3><<<grid, 256, SMEMI>>>(act3, bfi + 2*4608, A + 3*CC, B + 3*CC, act2, act4);
    // expand codes -> fp32 NCHW
    out_expand_kernel<<<16*196, 256>>>(act4, out);
}

// round 11
// speedup vs baseline: 1.3141x; 1.2545x over previous
#include <cuda_runtime.h>
#include <cuda_fp16.h>

#define NN 16
#define CC 64
#define HH 112
#define WW 112
#define HWHW (HH*WW)               // 12544
#define PKW (NN*16*HWHW)           // u8-packed NHWC act words
#define XHW (NN*HWHW*32)           // f16-packed x words (hi/mid/lo)

#define R_S  (10.0f/255.0f)
#define HT_S (10.0f/127.0f)
#define SC_M (1.0f/2048.0f)        // 2^-11
#define SC_L (1.0f/4194304.0f)     // 2^-22

// -------- device scratch ----------
__device__ unsigned g_act1[PKW];
__device__ unsigned g_act2[PKW];
__device__ unsigned g_act3[PKW];
__device__ unsigned g_act4[PKW];
__device__ unsigned g_idq [PKW];
__device__ unsigned g_xhi [XHW];
__device__ unsigned g_xmid[XHW];
__device__ unsigned g_xlo [XHW];
__device__ __align__(16) uint2 g_bfi[3*9*2*8*32];   // int-stage B fragments
__device__ __align__(16) uint2 g_bfh[9*4*8*32];     // stage0 f16 B fragments
__device__ float    g_dsq [CC*CC];
__device__ float    g_wsc [4*CC];
__device__ float    g_A   [4*CC];
__device__ float    g_B   [4*CC];
__device__ float    g_bninv4 [CC];
__device__ float    g_bnbias4[CC];

// ================= mma wrappers =================
__device__ __forceinline__ void mma_s8(int* d, unsigned a0, unsigned a1, unsigned a2,
                                       unsigned a3, unsigned b0, unsigned b1) {
    asm volatile("mma.sync.aligned.m16n8k32.row.col.s32.u8.s8.s32 "
        "{%0,%1,%2,%3}, {%4,%5,%6,%7}, {%8,%9}, {%0,%1,%2,%3};"
        : "+r"(d[0]), "+r"(d[1]), "+r"(d[2]), "+r"(d[3])
        : "r"(a0), "r"(a1), "r"(a2), "r"(a3), "r"(b0), "r"(b1));
}
__device__ __forceinline__ void mma_f16(float* d, unsigned a0, unsigned a1, unsigned a2,
                                        unsigned a3, unsigned b0, unsigned b1) {
    asm volatile("mma.sync.aligned.m16n8k16.row.col.f32.f16.f16.f32 "
        "{%0,%1,%2,%3}, {%4,%5,%6,%7}, {%8,%9}, {%0,%1,%2,%3};"
        : "+f"(d[0]), "+f"(d[1]), "+f"(d[2]), "+f"(d[3])
        : "r"(a0), "r"(a1), "r"(a2), "r"(a3), "r"(b0), "r"(b1));
}

// ================= quantizers (round-half-even, match jnp) =================
__device__ __forceinline__ float qhtanh_f(float x) {
    float c = fminf(fmaxf(x, -10.0f), 10.0f);
    float r = rintf(__fdiv_rn(c, HT_S));
    r = fminf(fmaxf(r, -127.0f), 127.0f);
    return r * HT_S;
}
__device__ __forceinline__ unsigned qrelu_code(float x) {
    float c = fminf(fmaxf(x, 0.0f), 10.0f);
    float r = rintf(__fdiv_rn(c, R_S));
    return (unsigned)(int)fminf(r, 255.0f);
}
__device__ __forceinline__ unsigned long long pack_dup(float v) {
    unsigned long long r;
    asm("mov.b64 %0, {%1, %1};" : "=l"(r) : "f"(v));
    return r;
}
__device__ __forceinline__ unsigned long long fma2(unsigned long long a, unsigned long long b,
                                                   unsigned long long c) {
    unsigned long long d;
    asm("fma.rn.f32x2 %0, %1, %2, %3;" : "=l"(d) : "l"(a), "l"(b), "l"(c));
    return d;
}
__device__ __forceinline__ void unpack2(unsigned long long v, float& lo, float& hi) {
    asm("mov.b64 {%0, %1}, %2;" : "=f"(lo), "=f"(hi) : "l"(v));
}

// ================= prep1: fused weight prep + x transpose (block roles) ======
// blocks [0,256)      : binary weight per-channel scale
// blocks [256,310)    : int-stage B fragments (13824 elems)
// blocks [310,346)    : stage0 f16 B fragments (9216 elems)
// blocks [346,410)    : int8 1x1 weight quant (one co per block)
// blocks [410,3546)   : x NCHW fp32 -> NHWC f16 hi/mid/lo (scaled exact split)
#define PREP1_GRID 3546
__global__ void prep1_kernel(const float* __restrict__ w, const float* __restrict__ ds_w,
                             const float* __restrict__ x,
                             float* __restrict__ wsc, uint2* __restrict__ bfi,
                             uint2* __restrict__ bfh, float* __restrict__ dsq,
                             unsigned* __restrict__ xhi, unsigned* __restrict__ xmid,
                             unsigned* __restrict__ xlo) {
    int b = blockIdx.x, tid = threadIdx.x;
    __shared__ float red[256];
    __shared__ unsigned short shi[64][66], smd[64][66], slo[64][66];

    if (b < 256) {                              // ---- weight scale (AVE)
        const float* wc = w + b*576;
        float s = 0.f;
        for (int e = tid; e < 576; e += 256) s += fabsf(wc[e]);
        red[tid] = s;
        __syncthreads();
        for (int off = 128; off > 0; off >>= 1) {
            if (tid < off) red[tid] += red[tid+off];
            __syncthreads();
        }
        if (tid == 0) wsc[b] = fmaxf(red[0] * (1.0f/576.0f), 2e-16f);
    } else if (b < 310) {                       // ---- int-stage B fragments
        int idx = (b-256)*256 + tid;
        if (idx < 3*9*2*8*32) {
            int lane = idx & 31;
            int nt   = (idx >> 5) & 7;
            int c    = (idx >> 8) & 1;
            int tap  = (idx >> 9) % 9;
            int s    = idx / 4608;
            int co   = nt*8 + (lane >> 2);
            unsigned b0 = 0, b1 = 0;
            #pragma unroll
            for (int j = 0; j < 4; j++) {
                int ci0 = c*32 + (lane & 3)*4 + j;
                float v0 = w[(((s+1)*64 + co)*64 + ci0)*9 + tap];
                float v1 = w[(((s+1)*64 + co)*64 + ci0 + 16)*9 + tap];
                b0 |= ((v0 >= 0.f) ? 0x01u : 0xFFu) << (8*j);
                b1 |= ((v1 >= 0.f) ? 0x01u : 0xFFu) << (8*j);
            }
            bfi[idx] = make_uint2(b0, b1);
        }
    } else if (b < 346) {                       // ---- stage0 f16 B fragments
        int idx = (b-310)*256 + tid;
        if (idx < 9*4*8*32) {
            int lane = idx & 31;
            int nt   = (idx >> 5) & 7;
            int c    = (idx >> 8) & 3;
            int tap  = idx >> 10;
            int co   = nt*8 + (lane >> 2);
            int ci   = c*16 + (lane & 3)*2;
            unsigned h00 = (w[((0*64+co)*64 + ci  )*9 + tap] >= 0.f) ? 0x3C00u : 0xBC00u;
            unsigned h01 = (w[((0*64+co)*64 + ci+1)*9 + tap] >= 0.f) ? 0x3C00u : 0xBC00u;
            unsigned h10 = (w[((0*64+co)*64 + ci+8)*9 + tap] >= 0.f) ? 0x3C00u : 0xBC00u;
            unsigned h11 = (w[((0*64+co)*64 + ci+9)*9 + tap] >= 0.f) ? 0x3C00u : 0xBC00u;
            bfh[idx] = make_uint2(h00 | (h01 << 16), h10 | (h11 << 16));
        }
    } else if (b < 410) {                       // ---- int8 1x1 quant
        int co = b - 346;
        red[tid] = (tid < 64) ? fabsf(ds_w[co*64 + tid]) : 0.f;
        __syncthreads();
        for (int off = 128; off > 0; off >>= 1) {
            if (tid < off) red[tid] = fmaxf(red[tid], red[tid+off]);
            __syncthreads();
        }
        if (tid < 64) {
            float scale = fmaxf(red[0], 2e-16f) / 127.0f;
            float q = fminf(fmaxf(rintf(__fdiv_rn(ds_w[co*64 + tid], scale)), -127.f), 127.f) * scale;
            dsq[tid*64 + co] = q;
        }
    } else {                                    // ---- transpose x -> hi/mid/lo
        int blk = b - 410;                      // 0..3135
        int n = blk / 196;
        int pix0 = (blk % 196) * 64;
        #pragma unroll
        for (int pass = 0; pass < 16; pass++) {
            int idx = tid + pass*256;
            int c = idx >> 6, p = idx & 63;
            float v = x[((size_t)n*64 + c)*HWHW + pix0 + p];
            __half h = __float2half_rn(v);
            float r1 = v - __half2float(h);
            __half m = __float2half_rn(r1 * 2048.0f);
            float r2 = r1 - __half2float(m) * SC_M;
            __half l = __float2half_rn(r2 * 4194304.0f);
            shi[p][c] = __half_as_ushort(h);
            smd[p][c] = __half_as_ushort(m);
            slo[p][c] = __half_as_ushort(l);
        }
        __syncthreads();
        int px = tid >> 2, part = tid & 3;
        size_t base = ((size_t)n*HWHW + pix0 + px)*32 + part*8;
        #pragma unroll
        for (int i = 0; i < 8; i++) {
            int c = part*16 + i*2;
            xhi [base+i] = (unsigned)shi[px][c] | ((unsigned)shi[px][c+1] << 16);
            xmid[base+i] = (unsigned)smd[px][c] | ((unsigned)smd[px][c+1] << 16);
            xlo [base+i] = (unsigned)slo[px][c] | ((unsigned)slo[px][c+1] << 16);
        }
    }
}

// ================= prep2: BN coefficients =================
__global__ void prep2_kernel(const float* __restrict__ g, const float* __restrict__ b,
                             const float* __restrict__ m, const float* __restrict__ v,
                             const float* __restrict__ wsc,
                             float* __restrict__ A, float* __restrict__ B,
                             float* __restrict__ inv4, float* __restrict__ bias4) {
    int i = threadIdx.x;   // 320
    float iv = g[i] * __fdiv_rn(1.0f, __fsqrt_rn(v[i] + 1e-5f));
    float bias = b[i] - m[i] * iv;
    if (i < 256) {
        int s = i >> 6;
        float a = wsc[i] * iv;
        if (s > 0) a *= R_S;
        A[i] = a;
        B[i] = bias;
    } else {
        inv4[i-256] = iv;
        bias4[i-256] = bias;
    }
}

// -------- 1x1 conv (downsample) + bn4 + qhtanh -> NHWC packed s8 ------
__global__ __launch_bounds__(256, 2)
void conv1x1_kernel(const float* __restrict__ x, const float* __restrict__ wt,
                    const float* __restrict__ bninv, const float* __restrict__ bnbias,
                    unsigned* __restrict__ out) {
    int b  = blockIdx.x;          // 784 = 16 * 49
    int n  = b / 49;
    int p0 = (b - n*49) * 256;
    __shared__ float xs[16][256];
    __shared__ __align__(8) float ws[16][64];
    __shared__ unsigned s_out[256][16];
    int t   = threadIdx.x;
    int pl  = t & 63;
    int cog = t >> 6;
    unsigned long long acc2[4][8];
    #pragma unroll
    for (int j = 0; j < 4; j++)
        #pragma unroll
        for (int k2 = 0; k2 < 8; k2++) acc2[j][k2] = 0ULL;

    const float* xN = x + (size_t)n*CC*HWHW + p0;
    for (int c0 = 0; c0 < CC; c0 += 16) {
        __syncthreads();
        #pragma unroll
        for (int r = 0; r < 16; r++) xs[r][t] = xN[(size_t)(c0+r)*HWHW + t];
        #pragma unroll
        for (int r = 0; r < 4; r++) {
            int e = t + r*256;
            ws[e>>6][e&63] = wt[(c0 + (e>>6))*64 + (e&63)];
        }
        __syncthreads();
        #pragma unroll
        for (int ci = 0; ci < 16; ci++) {
            unsigned long long w2[8];
            #pragma unroll
            for (int k2 = 0; k2 < 8; k2++)
                w2[k2] = *(const unsigned long long*)&ws[ci][cog*16 + 2*k2];
            #pragma unroll
            for (int j = 0; j < 4; j++) {
                unsigned long long xv2 = pack_dup(xs[ci][pl + 64*j]);
                #pragma unroll
                for (int k2 = 0; k2 < 8; k2++)
                    acc2[j][k2] = fma2(xv2, w2[k2], acc2[j][k2]);
            }
        }
    }
    #pragma unroll
    for (int j = 0; j < 4; j++) {
        unsigned words[4] = {0,0,0,0};
        #pragma unroll
        for (int k2 = 0; k2 < 8; k2++) {
            float a0, a1;
            unpack2(acc2[j][k2], a0, a1);
            #pragma unroll
            for (int h = 0; h < 2; h++) {
                int k = 2*k2 + h;
                int co = cog*16 + k;
                float v = fmaf(h ? a1 : a0, bninv[co], bnbias[co]);
                float c = fminf(fmaxf(v, -10.0f), 10.0f);
                float r = fminf(fmaxf(rintf(__fdiv_rn(c, HT_S)), -127.f), 127.f);
                words[k>>2] |= (((unsigned)(int)r) & 0xFFu) << (8*(k&3));
            }
        }
        #pragma unroll
        for (int q = 0; q < 4; q++) s_out[pl + 64*j][cog*4 + q] = words[q];
    }
    __syncthreads();
    uint4* gdst = (uint4*)(out + ((size_t)n*HWHW + p0 + t)*16);
    const uint4* srow = (const uint4*)&s_out[t][0];
    #pragma unroll
    for (int q = 0; q < 4; q++) gdst[q] = srow[q];
}

// ================ HMMA stage 0: single halo, 3 streamed passes ================
// smem: sB uint2[9216] (73728B) | halo u32[180][34] (24480B)  => 98208B, 2 CTAs/SM
// pass order lo -> mid -> hi; acc *= 2^-11 between passes (exact power-of-2).
#define HPITCH_H 34
__global__ __launch_bounds__(256, 2)
void conv3x3_hmma0(const unsigned* __restrict__ xhi, const unsigned* __restrict__ xmid,
                   const unsigned* __restrict__ xlo,
                   const uint2* __restrict__ bfrag,
                   const float* __restrict__ Acoef, const float* __restrict__ Bcoef,
                   unsigned* __restrict__ outp) {
    extern __shared__ char dsm[];
    uint2* sBf = (uint2*)dsm;
    unsigned* halo = (unsigned*)(dsm + 73728);
    __shared__ float sAc[64], sBc[64];

    int tid = threadIdx.x;
    int wid = tid >> 5;
    int lane = tid & 31;
    int n  = blockIdx.z;
    int h0 = blockIdx.y * 8;
    int w0 = blockIdx.x * 16;

    if (tid < 64) { sAc[tid] = Acoef[tid]; sBc[tid] = Bcoef[tid]; }
    {
        const uint4* src = (const uint4*)bfrag;
        uint4* dst = (uint4*)sBf;
        #pragma unroll
        for (int i = 0; i < 18; i++) dst[tid + i*256] = src[tid + i*256];
    }

    float acc[8][4];
    #pragma unroll
    for (int nt = 0; nt < 8; nt++)
        #pragma unroll
        for (int q = 0; q < 4; q++) acc[nt][q] = 0.f;

    #pragma unroll 1
    for (int pass = 0; pass < 3; pass++) {
        const unsigned* xsrc = (pass == 0) ? xlo : (pass == 1) ? xmid : xhi;
        __syncthreads();          // prior pass reads done (and sBf copy on pass 0)
        for (int e = tid; e < 5760; e += 256) {
            int r = e / 576, rr = e % 576, c = rr >> 5, q = rr & 31;
            int hh = h0 - 1 + r, ww = w0 - 1 + c;
            unsigned v = 0;
            if ((unsigned)hh < HH && (unsigned)ww < WW)
                v = xsrc[((size_t)n*HWHW + (size_t)hh*WW + ww)*32 + q];
            halo[(r*18 + c)*HPITCH_H + q] = v;
        }
        __syncthreads();
        #pragma unroll 1
        for (int dy = 0; dy < 3; dy++)
        #pragma unroll
        for (int dx = 0; dx < 3; dx++) {
            int rbase = ((wid + dy)*18 + (lane >> 2) + dx)*HPITCH_H;
            #pragma unroll
            for (int c = 0; c < 4; c++) {
                unsigned a0 = halo[rbase + c*8 + (lane & 3)];
                unsigned a2 = halo[rbase + c*8 + 4 + (lane & 3)];
                unsigned a1 = halo[rbase + 8*HPITCH_H + c*8 + (lane & 3)];
                unsigned a3 = halo[rbase + 8*HPITCH_H + c*8 + 4 + (lane & 3)];
                const uint2* bp = sBf + ((dy*3 + dx)*4 + c)*256 + lane;
                #pragma unroll
                for (int nt = 0; nt < 8; nt++) {
                    uint2 b = bp[nt*32];
                    mma_f16(acc[nt], a0, a1, a2, a3, b.x, b.y);
                }
            }
        }
        if (pass < 2) {
            #pragma unroll
            for (int nt = 0; nt < 8; nt++)
                #pragma unroll
                for (int q = 0; q < 4; q++) acc[nt][q] *= SC_M;
        }
    }

    // epilogue: D = acc;  x = (hi + mid*2^-11) + lo*2^-22 read from gmem (exact)
    unsigned short pairs[2][8];
    #pragma unroll
    for (int h2 = 0; h2 < 2; h2++) {
        int px = (lane >> 2) + 8*h2;
        size_t gw = ((size_t)n*HWHW + (size_t)(h0 + wid)*WW + (w0 + px))*32 + (lane & 3);
        #pragma unroll
        for (int nt = 0; nt < 8; nt++) {
            unsigned wh = __ldg(xhi  + gw + nt*4);
            unsigned wm = __ldg(xmid + gw + nt*4);
            unsigned wl = __ldg(xlo  + gw + nt*4);
            unsigned pr = 0;
            #pragma unroll
            for (int j = 0; j < 2; j++) {
                int co = nt*8 + (lane & 3)*2 + j;
                float v = fmaf(acc[nt][2*h2 + j], sAc[co], sBc[co]);
                __half xh = __ushort_as_half((unsigned short)((wh >> (16*j)) & 0xFFFF));
                __half xm = __ushort_as_half((unsigned short)((wm >> (16*j)) & 0xFFFF));
                __half xl = __ushort_as_half((unsigned short)((wl >> (16*j)) & 0xFFFF));
                float xv = (__half2float(xh) + __half2float(xm) * SC_M)
                         + __half2float(xl) * SC_L;
                float r = qhtanh_f(v) + qhtanh_f(xv);
                pr |= qrelu_code(r) << (8*j);
            }
            pairs[h2][nt] = (unsigned short)pr;
        }
    }
    __syncthreads();
    unsigned short* stag = (unsigned short*)halo;
    #pragma unroll
    for (int h2 = 0; h2 < 2; h2++) {
        int px = (lane >> 2) + 8*h2;
        int pxl = wid*16 + px;
        #pragma unroll
        for (int nt = 0; nt < 8; nt++)
            stag[pxl*32 + nt*4 + (lane & 3)] = pairs[h2][nt];
    }
    __syncthreads();
    {
        int pxl = tid >> 1, half = tid & 1;
        int h = h0 + (pxl >> 4), w = w0 + (pxl & 15);
        const uint4* src = (const uint4*)((char*)halo + pxl*64 + half*32);
        uint4* dst = (uint4*)(outp + ((size_t)n*HWHW + (size_t)h*WW + w)*16 + half*8);
        dst[0] = src[0];
        dst[1] = src[1];
    }
}

// ================ IMMA int stages (EPI 0/1/3) ================
// smem: sB uint2[4608] (36864B) | halo u32[10*18 px][17] (12240B, reused as staging)
#define HPITCH_I 17
template<int EPI>
__global__ __launch_bounds__(256, 3)
void conv3x3_imma(const unsigned* __restrict__ act_in, const uint2* __restrict__ bfrag,
                  const float* __restrict__ Acoef, const float* __restrict__ Bcoef,
                  const unsigned* __restrict__ e1, unsigned* __restrict__ outp) {
    extern __shared__ char dsm[];
    uint2* sBf = (uint2*)dsm;
    unsigned* halo = (unsigned*)(dsm + 36864);
    __shared__ float sAc[64], sBc[64];

    int tid = threadIdx.x;
    int wid = tid >> 5;
    int lane = tid & 31;
    int n  = blockIdx.z;
    int h0 = blockIdx.y * 8;
    int w0 = blockIdx.x * 16;

    if (tid < 64) { sAc[tid] = Acoef[tid]; sBc[tid] = Bcoef[tid]; }
    {
        const uint4* src = (const uint4*)bfrag;
        uint4* dst = (uint4*)sBf;
        #pragma unroll
        for (int i = 0; i < 9; i++) dst[tid + i*256] = src[tid + i*256];
    }
    const unsigned* inN = act_in + (size_t)n*HWHW*16;
    for (int e = tid; e < 2880; e += 256) {
        int r = e / 288, rr = e % 288, c = rr >> 4, q = rr & 15;
        int hh = h0 - 1 + r, ww = w0 - 1 + c;
        unsigned v = 0;
        if ((unsigned)hh < HH && (unsigned)ww < WW)
            v = inN[((size_t)hh*WW + ww)*16 + q];
        halo[(r*18 + c)*HPITCH_I + q] = v;
    }
    __syncthreads();

    int acc[8][4];
    #pragma unroll
    for (int nt = 0; nt < 8; nt++)
        #pragma unroll
        for (int q = 0; q < 4; q++) acc[nt][q] = 0;

    #pragma unroll 1
    for (int dy = 0; dy < 3; dy++)
    #pragma unroll
    for (int dx = 0; dx < 3; dx++) {
        int rbase = ((wid + dy)*18 + (lane >> 2) + dx)*HPITCH_I;
        #pragma unroll
        for (int c = 0; c < 2; c++) {
            unsigned a0 = halo[rbase + c*8 + (lane & 3)];
            unsigned a2 = halo[rbase + c*8 + 4 + (lane & 3)];
            unsigned a1 = halo[rbase + 8*HPITCH_I + c*8 + (lane & 3)];
            unsigned a3 = halo[rbase + 8*HPITCH_I + c*8 + 4 + (lane & 3)];
            const uint2* bp = sBf + ((dy*3 + dx)*2 + c)*256 + lane;
            #pragma unroll
            for (int nt = 0; nt < 8; nt++) {
                uint2 b = bp[nt*32];
                mma_s8(acc[nt], a0, a1, a2, a3, b.x, b.y);
            }
        }
    }

    // epilogue -> u8 code pairs
    unsigned short pairs[2][8];
    int ctr_row = (wid + 1)*18;
    #pragma unroll
    for (int h2 = 0; h2 < 2; h2++) {
        int px = (lane >> 2) + 8*h2;
        int ctr = (ctr_row + px + 1)*HPITCH_I;
        size_t pixw = ((size_t)n*HWHW + (size_t)(h0 + wid)*WW + (w0 + px))*16;
        int wsel = (lane & 3) >> 1;
        int b0 = ((lane & 3) & 1)*2;
        #pragma unroll
        for (int nt = 0; nt < 8; nt++) {
            unsigned inw = halo[ctr + 2*nt + wsel];
            unsigned ew = 0;
            if (EPI == 1 || EPI == 3) ew = e1[pixw + 2*nt + wsel];
            unsigned pr = 0;
            #pragma unroll
            for (int j = 0; j < 2; j++) {
                int co = nt*8 + (lane & 3)*2 + j;
                float v = fmaf((float)acc[nt][2*h2 + j], sAc[co], sBc[co]);
                int byte = b0 + j;
                float in_val = (float)((inw >> (8*byte)) & 255u) * R_S;
                float r;
                if (EPI == 0) {
                    r = qhtanh_f(v) + qhtanh_f(in_val);
                } else if (EPI == 1) {
                    int ec = (int)(ew << (24 - 8*byte)) >> 24;
                    float tq = qhtanh_f(v) + (float)ec * HT_S;
                    r = qhtanh_f(tq) + qhtanh_f(in_val);
                } else {
                    float ev = (float)((ew >> (8*byte)) & 255u) * R_S;
                    float tq = qhtanh_f(v) + qhtanh_f(ev);
                    r = qhtanh_f(in_val) + qhtanh_f(tq);
                }
                pr |= qrelu_code(r) << (8*j);
            }
            pairs[h2][nt] = (unsigned short)pr;
        }
    }
    __syncthreads();                       // all halo reads done; reuse as staging
    unsigned short* stag = (unsigned short*)halo;
    #pragma unroll
    for (int h2 = 0; h2 < 2; h2++) {
        int px = (lane >> 2) + 8*h2;
        int pxl = wid*16 + px;
        #pragma unroll
        for (int nt = 0; nt < 8; nt++)
            stag[pxl*32 + nt*4 + (lane & 3)] = pairs[h2][nt];
    }
    __syncthreads();
    {
        int pxl = tid >> 1, half = tid & 1;
        int h = h0 + (pxl >> 4), w = w0 + (pxl & 15);
        const uint4* src = (const uint4*)((char*)halo + pxl*64 + half*32);
        uint4* dst = (uint4*)(outp + ((size_t)n*HWHW + (size_t)h*WW + w)*16 + half*8);
        dst[0] = src[0];
        dst[1] = src[1];
    }
}

// -------- final: u8 NHWC codes -> fp32 NCHW (out = code * R_S) --------
__global__ void out_expand_kernel(const unsigned* __restrict__ codes,
                                  float* __restrict__ out) {
    __shared__ unsigned st[64][17];
    int blk = blockIdx.x;             // 16*196
    int n = blk / 196;
    int pix0 = (blk % 196) * 64;
    int tid = threadIdx.x;
    #pragma unroll
    for (int i = 0; i < 4; i++) {
        int e = tid + i*256;
        int px = e >> 4, q = e & 15;
        st[px][q] = codes[((size_t)n*HWHW + pix0 + px)*16 + q];
    }
    __syncthreads();
    int c = tid >> 2, qq = tid & 3;
    float* dst = out + ((size_t)n*64 + c)*HWHW + pix0 + qq*16;
    #pragma unroll
    for (int i = 0; i < 16; i++) {
        unsigned w = st[qq*16 + i][c >> 2];
        dst[i] = (float)((w >> (8*(c & 3))) & 255u) * R_S;
    }
}

// -------------------- host launcher --------------------------------
extern "C" void kernel_launch(void* const* d_in, const int* in_sizes, int n_in,
                              void* d_out, int out_size) {
    const float* x      = (const float*)d_in[0];
    const float* conv_w = (const float*)d_in[1];
    const float* ds_w   = (const float*)d_in[2];
    const float* bng    = (const float*)d_in[3];
    const float* bnb    = (const float*)d_in[4];
    const float* bnm    = (const float*)d_in[5];
    const float* bnvv   = (const float*)d_in[6];
    float* out = (float*)d_out;

    unsigned *act1, *act2, *act3, *act4, *idq, *xhi, *xmid, *xlo;
    uint2 *bfi, *bfh;
    float *dsq, *wsc, *A, *B, *inv4, *bias4;
    cudaGetSymbolAddress((void**)&act1, g_act1);
    cudaGetSymbolAddress((void**)&act2, g_act2);
    cudaGetSymbolAddress((void**)&act3, g_act3);
    cudaGetSymbolAddress((void**)&act4, g_act4);
    cudaGetSymbolAddress((void**)&idq,  g_idq);
    cudaGetSymbolAddress((void**)&xhi,  g_xhi);
    cudaGetSymbolAddress((void**)&xmid, g_xmid);
    cudaGetSymbolAddress((void**)&xlo,  g_xlo);
    cudaGetSymbolAddress((void**)&bfi,  g_bfi);
    cudaGetSymbolAddress((void**)&bfh,  g_bfh);
    cudaGetSymbolAddress((void**)&dsq,  g_dsq);
    cudaGetSymbolAddress((void**)&wsc,  g_wsc);
    cudaGetSymbolAddress((void**)&A,    g_A);
    cudaGetSymbolAddress((void**)&B,    g_B);
    cudaGetSymbolAddress((void**)&inv4, g_bninv4);
    cudaGetSymbolAddress((void**)&bias4,g_bnbias4);

    const int SMEMI = 36864 + 12240;            // 49,104
    const int SMEM0 = 73728 + 24480;            // 98,208 -> 2 CTAs/SM
    cudaFuncSetAttribute(conv3x3_hmma0,   cudaFuncAttributeMaxDynamicSharedMemorySize, SMEM0);
    cudaFuncSetAttribute(conv3x3_imma<0>, cudaFuncAttributeMaxDynamicSharedMemorySize, SMEMI);
    cudaFuncSetAttribute(conv3x3_imma<1>, cudaFuncAttributeMaxDynamicSharedMemorySize, SMEMI);
    cudaFuncSetAttribute(conv3x3_imma<3>, cudaFuncAttributeMaxDynamicSharedMemorySize, SMEMI);

    // launch #1: fused prep; #2: bn coefs; #3: conv1x1; #4: hmma0 (profiled)
    prep1_kernel<<<PREP1_GRID, 256>>>(conv_w, ds_w, x, wsc, bfi, bfh, dsq, xhi, xmid, xlo);
    prep2_kernel<<<1, 320>>>(bng, bnb, bnm, bnvv, wsc, A, B, inv4, bias4);
    conv1x1_kernel<<<784, 256>>>(x, dsq, inv4, bias4, idq);

    dim3 grid(7, 14, NN);   // 16w x 8h tiles
    conv3x3_hmma0<<<grid, 256, SMEM0>>>(xhi, xmid, xlo, bfh, A + 0*CC, B + 0*CC, act1);
    conv3x3_imma<1><<<grid, 256, SMEMI>>>(act1, bfi + 0*4608, A + 1*CC, B + 1*CC, idq,  act2);
    conv3x3_imma<0><<<grid, 256, SMEMI>>>(act2, bfi + 1*4608, A + 2*CC, B + 2*CC, nullptr, act3);
    conv3x3_imma<3><<<grid, 256, SMEMI>>>(act3, bfi + 2*4608, A + 3*CC, B + 3*CC, act2, act4);
    out_expand_kernel<<<16*196, 256>>>(act4, out);
}

// round 12
// speedup vs baseline: 1.3429x; 1.0219x over previous
#include <cuda_runtime.h>
#include <cuda_fp16.h>

#define NN 16
#define CC 64
#define HH 112
#define WW 112
#define HWHW (HH*WW)               // 12544
#define PKW (NN*16*HWHW)           // u8-packed NHWC act words
#define XHW (NN*HWHW*32)           // f16-packed x words (hi/mid/lo)

#define R_S  (10.0f/255.0f)
#define HT_S (10.0f/127.0f)
#define SC_M (1.0f/2048.0f)        // 2^-11
#define SC_L (1.0f/4194304.0f)     // 2^-22

// -------- device scratch ----------
__device__ unsigned g_act1[PKW];
__device__ unsigned g_act2[PKW];
__device__ unsigned g_act3[PKW];
__device__ unsigned g_act4[PKW];
__device__ unsigned g_idq [PKW];
__device__ unsigned g_xhi [XHW];
__device__ unsigned g_xmid[XHW];
__device__ unsigned g_xlo [XHW];
__device__ __align__(16) uint2 g_bfi[3*9*2*8*32];   // int-stage B fragments
__device__ __align__(16) uint2 g_bfh[9*4*8*32];     // stage0 f16 B fragments
__device__ float    g_dsq [CC*CC];
__device__ float    g_wsc [4*CC];
__device__ float    g_A   [4*CC];
__device__ float    g_B   [4*CC];
__device__ float    g_bninv4 [CC];
__device__ float    g_bnbias4[CC];

// ================= helpers =================
__device__ __forceinline__ unsigned smem_u32(const void* p) {
    unsigned a;
    asm("{ .reg .u64 t; cvta.to.shared.u64 t, %1; cvt.u32.u64 %0, t; }" : "=r"(a) : "l"(p));
    return a;
}
__device__ __forceinline__ void ldsm_x4(unsigned& r0, unsigned& r1, unsigned& r2,
                                        unsigned& r3, unsigned addr) {
    asm volatile("ldmatrix.sync.aligned.m8n8.x4.shared.b16 {%0,%1,%2,%3}, [%4];"
        : "=r"(r0), "=r"(r1), "=r"(r2), "=r"(r3) : "r"(addr));
}
__device__ __forceinline__ void mma_s8(int* d, unsigned a0, unsigned a1, unsigned a2,
                                       unsigned a3, unsigned b0, unsigned b1) {
    asm volatile("mma.sync.aligned.m16n8k32.row.col.s32.u8.s8.s32 "
        "{%0,%1,%2,%3}, {%4,%5,%6,%7}, {%8,%9}, {%0,%1,%2,%3};"
        : "+r"(d[0]), "+r"(d[1]), "+r"(d[2]), "+r"(d[3])
        : "r"(a0), "r"(a1), "r"(a2), "r"(a3), "r"(b0), "r"(b1));
}
__device__ __forceinline__ void mma_f16(float* d, unsigned a0, unsigned a1, unsigned a2,
                                        unsigned a3, unsigned b0, unsigned b1) {
    asm volatile("mma.sync.aligned.m16n8k16.row.col.f32.f16.f16.f32 "
        "{%0,%1,%2,%3}, {%4,%5,%6,%7}, {%8,%9}, {%0,%1,%2,%3};"
        : "+f"(d[0]), "+f"(d[1]), "+f"(d[2]), "+f"(d[3])
        : "r"(a0), "r"(a1), "r"(a2), "r"(a3), "r"(b0), "r"(b1));
}

// ================= quantizers (round-half-even, match jnp) =================
__device__ __forceinline__ float qhtanh_f(float x) {
    float c = fminf(fmaxf(x, -10.0f), 10.0f);
    float r = rintf(__fdiv_rn(c, HT_S));
    r = fminf(fmaxf(r, -127.0f), 127.0f);
    return r * HT_S;
}
__device__ __forceinline__ unsigned qrelu_code(float x) {
    float c = fminf(fmaxf(x, 0.0f), 10.0f);
    float r = rintf(__fdiv_rn(c, R_S));
    return (unsigned)(int)fminf(r, 255.0f);
}
__device__ __forceinline__ unsigned long long pack_dup(float v) {
    unsigned long long r;
    asm("mov.b64 %0, {%1, %1};" : "=l"(r) : "f"(v));
    return r;
}
__device__ __forceinline__ unsigned long long fma2(unsigned long long a, unsigned long long b,
                                                   unsigned long long c) {
    unsigned long long d;
    asm("fma.rn.f32x2 %0, %1, %2, %3;" : "=l"(d) : "l"(a), "l"(b), "l"(c));
    return d;
}
__device__ __forceinline__ void unpack2(unsigned long long v, float& lo, float& hi) {
    asm("mov.b64 {%0, %1}, %2;" : "=f"(lo), "=f"(hi) : "l"(v));
}

// ================= prep1: fused weight prep + x transpose (block roles) ======
#define PREP1_GRID 3546
__global__ void prep1_kernel(const float* __restrict__ w, const float* __restrict__ ds_w,
                             const float* __restrict__ x,
                             float* __restrict__ wsc, uint2* __restrict__ bfi,
                             uint2* __restrict__ bfh, float* __restrict__ dsq,
                             unsigned* __restrict__ xhi, unsigned* __restrict__ xmid,
                             unsigned* __restrict__ xlo) {
    int b = blockIdx.x, tid = threadIdx.x;
    __shared__ float red[256];
    __shared__ unsigned short shi[64][66], smd[64][66], slo[64][66];

    if (b < 256) {                              // ---- weight scale (AVE)
        const float* wc = w + b*576;
        float s = 0.f;
        for (int e = tid; e < 576; e += 256) s += fabsf(wc[e]);
        red[tid] = s;
        __syncthreads();
        for (int off = 128; off > 0; off >>= 1) {
            if (tid < off) red[tid] += red[tid+off];
            __syncthreads();
        }
        if (tid == 0) wsc[b] = fmaxf(red[0] * (1.0f/576.0f), 2e-16f);
    } else if (b < 310) {                       // ---- int-stage B fragments
        int idx = (b-256)*256 + tid;
        if (idx < 3*9*2*8*32) {
            int lane = idx & 31;
            int nt   = (idx >> 5) & 7;
            int c    = (idx >> 8) & 1;
            int tap  = (idx >> 9) % 9;
            int s    = idx / 4608;
            int co   = nt*8 + (lane >> 2);
            unsigned b0 = 0, b1 = 0;
            #pragma unroll
            for (int j = 0; j < 4; j++) {
                int ci0 = c*32 + (lane & 3)*4 + j;
                float v0 = w[(((s+1)*64 + co)*64 + ci0)*9 + tap];
                float v1 = w[(((s+1)*64 + co)*64 + ci0 + 16)*9 + tap];
                b0 |= ((v0 >= 0.f) ? 0x01u : 0xFFu) << (8*j);
                b1 |= ((v1 >= 0.f) ? 0x01u : 0xFFu) << (8*j);
            }
            bfi[idx] = make_uint2(b0, b1);
        }
    } else if (b < 346) {                       // ---- stage0 f16 B fragments
        int idx = (b-310)*256 + tid;
        if (idx < 9*4*8*32) {
            int lane = idx & 31;
            int nt   = (idx >> 5) & 7;
            int c    = (idx >> 8) & 3;
            int tap  = idx >> 10;
            int co   = nt*8 + (lane >> 2);
            int ci   = c*16 + (lane & 3)*2;
            unsigned h00 = (w[((0*64+co)*64 + ci  )*9 + tap] >= 0.f) ? 0x3C00u : 0xBC00u;
            unsigned h01 = (w[((0*64+co)*64 + ci+1)*9 + tap] >= 0.f) ? 0x3C00u : 0xBC00u;
            unsigned h10 = (w[((0*64+co)*64 + ci+8)*9 + tap] >= 0.f) ? 0x3C00u : 0xBC00u;
            unsigned h11 = (w[((0*64+co)*64 + ci+9)*9 + tap] >= 0.f) ? 0x3C00u : 0xBC00u;
            bfh[idx] = make_uint2(h00 | (h01 << 16), h10 | (h11 << 16));
        }
    } else if (b < 410) {                       // ---- int8 1x1 quant
        int co = b - 346;
        red[tid] = (tid < 64) ? fabsf(ds_w[co*64 + tid]) : 0.f;
        __syncthreads();
        for (int off = 128; off > 0; off >>= 1) {
            if (tid < off) red[tid] = fmaxf(red[tid], red[tid+off]);
            __syncthreads();
        }
        if (tid < 64) {
            float scale = fmaxf(red[0], 2e-16f) / 127.0f;
            float q = fminf(fmaxf(rintf(__fdiv_rn(ds_w[co*64 + tid], scale)), -127.f), 127.f) * scale;
            dsq[tid*64 + co] = q;
        }
    } else {                                    // ---- transpose x -> hi/mid/lo
        int blk = b - 410;                      // 0..3135
        int n = blk / 196;
        int pix0 = (blk % 196) * 64;
        #pragma unroll
        for (int pass = 0; pass < 16; pass++) {
            int idx = tid + pass*256;
            int c = idx >> 6, p = idx & 63;
            float v = x[((size_t)n*64 + c)*HWHW + pix0 + p];
            __half h = __float2half_rn(v);
            float r1 = v - __half2float(h);
            __half m = __float2half_rn(r1 * 2048.0f);
            float r2 = r1 - __half2float(m) * SC_M;
            __half l = __float2half_rn(r2 * 4194304.0f);
            shi[p][c] = __half_as_ushort(h);
            smd[p][c] = __half_as_ushort(m);
            slo[p][c] = __half_as_ushort(l);
        }
        __syncthreads();
        int px = tid >> 2, part = tid & 3;
        size_t base = ((size_t)n*HWHW + pix0 + px)*32 + part*8;
        #pragma unroll
        for (int i = 0; i < 8; i++) {
            int c = part*16 + i*2;
            xhi [base+i] = (unsigned)shi[px][c] | ((unsigned)shi[px][c+1] << 16);
            xmid[base+i] = (unsigned)smd[px][c] | ((unsigned)smd[px][c+1] << 16);
            xlo [base+i] = (unsigned)slo[px][c] | ((unsigned)slo[px][c+1] << 16);
        }
    }
}

// ================= prep2: BN coefficients =================
__global__ void prep2_kernel(const float* __restrict__ g, const float* __restrict__ b,
                             const float* __restrict__ m, const float* __restrict__ v,
                             const float* __restrict__ wsc,
                             float* __restrict__ A, float* __restrict__ B,
                             float* __restrict__ inv4, float* __restrict__ bias4) {
    int i = threadIdx.x;   // 320
    float iv = g[i] * __fdiv_rn(1.0f, __fsqrt_rn(v[i] + 1e-5f));
    float bias = b[i] - m[i] * iv;
    if (i < 256) {
        int s = i >> 6;
        float a = wsc[i] * iv;
        if (s > 0) a *= R_S;
        A[i] = a;
        B[i] = bias;
    } else {
        inv4[i-256] = iv;
        bias4[i-256] = bias;
    }
}

// -------- 1x1 conv (downsample) + bn4 + qhtanh -> NHWC packed s8 ------
__global__ __launch_bounds__(256, 2)
void conv1x1_kernel(const float* __restrict__ x, const float* __restrict__ wt,
                    const float* __restrict__ bninv, const float* __restrict__ bnbias,
                    unsigned* __restrict__ out) {
    int b  = blockIdx.x;          // 784 = 16 * 49
    int n  = b / 49;
    int p0 = (b - n*49) * 256;
    __shared__ float xs[16][256];
    __shared__ __align__(8) float ws[16][64];
    __shared__ unsigned s_out[256][16];
    int t   = threadIdx.x;
    int pl  = t & 63;
    int cog = t >> 6;
    unsigned long long acc2[4][8];
    #pragma unroll
    for (int j = 0; j < 4; j++)
        #pragma unroll
        for (int k2 = 0; k2 < 8; k2++) acc2[j][k2] = 0ULL;

    const float* xN = x + (size_t)n*CC*HWHW + p0;
    for (int c0 = 0; c0 < CC; c0 += 16) {
        __syncthreads();
        #pragma unroll
        for (int r = 0; r < 16; r++) xs[r][t] = xN[(size_t)(c0+r)*HWHW + t];
        #pragma unroll
        for (int r = 0; r < 4; r++) {
            int e = t + r*256;
            ws[e>>6][e&63] = wt[(c0 + (e>>6))*64 + (e&63)];
        }
        __syncthreads();
        #pragma unroll
        for (int ci = 0; ci < 16; ci++) {
            unsigned long long w2[8];
            #pragma unroll
            for (int k2 = 0; k2 < 8; k2++)
                w2[k2] = *(const unsigned long long*)&ws[ci][cog*16 + 2*k2];
            #pragma unroll
            for (int j = 0; j < 4; j++) {
                unsigned long long xv2 = pack_dup(xs[ci][pl + 64*j]);
                #pragma unroll
                for (int k2 = 0; k2 < 8; k2++)
                    acc2[j][k2] = fma2(xv2, w2[k2], acc2[j][k2]);
            }
        }
    }
    #pragma unroll
    for (int j = 0; j < 4; j++) {
        unsigned words[4] = {0,0,0,0};
        #pragma unroll
        for (int k2 = 0; k2 < 8; k2++) {
            float a0, a1;
            unpack2(acc2[j][k2], a0, a1);
            #pragma unroll
            for (int h = 0; h < 2; h++) {
                int k = 2*k2 + h;
                int co = cog*16 + k;
                float v = fmaf(h ? a1 : a0, bninv[co], bnbias[co]);
                float c = fminf(fmaxf(v, -10.0f), 10.0f);
                float r = fminf(fmaxf(rintf(__fdiv_rn(c, HT_S)), -127.f), 127.f);
                words[k>>2] |= (((unsigned)(int)r) & 0xFFu) << (8*(k&3));
            }
        }
        #pragma unroll
        for (int q = 0; q < 4; q++) s_out[pl + 64*j][cog*4 + q] = words[q];
    }
    __syncthreads();
    uint4* gdst = (uint4*)(out + ((size_t)n*HWHW + p0 + t)*16);
    const uint4* srow = (const uint4*)&s_out[t][0];
    #pragma unroll
    for (int q = 0; q < 4; q++) gdst[q] = srow[q];
}

// ================ HMMA stage 0: single halo, 3 streamed passes ================
// halo pitch 36 u32 = 144B: ldmatrix rows land on banks 4r mod 32 -> conflict-free.
// smem: sB uint2[9216] (73728B) | halo u32[180][36] (25920B) => 99648B, 2 CTAs/SM
#define HPITCH_H 36
__global__ __launch_bounds__(256, 2)
void conv3x3_hmma0(const unsigned* __restrict__ xhi, const unsigned* __restrict__ xmid,
                   const unsigned* __restrict__ xlo,
                   const uint2* __restrict__ bfrag,
                   const float* __restrict__ Acoef, const float* __restrict__ Bcoef,
                   unsigned* __restrict__ outp) {
    extern __shared__ char dsm[];
    uint2* sBf = (uint2*)dsm;
    unsigned* halo = (unsigned*)(dsm + 73728);
    __shared__ float sAc[64], sBc[64];

    int tid = threadIdx.x;
    int wid = tid >> 5;
    int lane = tid & 31;
    int n  = blockIdx.z;
    int h0 = blockIdx.y * 8;
    int w0 = blockIdx.x * 16;

    if (tid < 64) { sAc[tid] = Acoef[tid]; sBc[tid] = Bcoef[tid]; }
    {
        const uint4* src = (const uint4*)bfrag;
        uint4* dst = (uint4*)sBf;
        #pragma unroll
        for (int i = 0; i < 18; i++) dst[tid + i*256] = src[tid + i*256];
    }
    // per-thread ldmatrix base address (tile row = pixel column, half = +16B)
    unsigned haloAddr = smem_u32(halo);
    unsigned aBase = haloAddr + (unsigned)((wid*18 + (lane & 15))*144 + (lane >> 4)*16);

    float acc[8][4];
    #pragma unroll
    for (int nt = 0; nt < 8; nt++)
        #pragma unroll
        for (int q = 0; q < 4; q++) acc[nt][q] = 0.f;

    #pragma unroll 1
    for (int pass = 0; pass < 3; pass++) {
        const unsigned* xsrc = (pass == 0) ? xlo : (pass == 1) ? xmid : xhi;
        __syncthreads();
        for (int e = tid; e < 5760; e += 256) {
            int r = e / 576, rr = e % 576, c = rr >> 5, q = rr & 31;
            int hh = h0 - 1 + r, ww = w0 - 1 + c;
            unsigned v = 0;
            if ((unsigned)hh < HH && (unsigned)ww < WW)
                v = xsrc[((size_t)n*HWHW + (size_t)hh*WW + ww)*32 + q];
            halo[(r*18 + c)*HPITCH_H + q] = v;
        }
        __syncthreads();
        #pragma unroll 1
        for (int dy = 0; dy < 3; dy++)
        #pragma unroll
        for (int dx = 0; dx < 3; dx++) {
            unsigned rowOff = aBase + (unsigned)((dy*18 + dx)*144);
            #pragma unroll
            for (int c = 0; c < 4; c++) {
                unsigned a0, a1, a2, a3;
                ldsm_x4(a0, a1, a2, a3, rowOff + c*32);
                const uint2* bp = sBf + ((dy*3 + dx)*4 + c)*256 + lane;
                #pragma unroll
                for (int nt = 0; nt < 8; nt++) {
                    uint2 b = bp[nt*32];
                    mma_f16(acc[nt], a0, a1, a2, a3, b.x, b.y);
                }
            }
        }
        if (pass < 2) {
            #pragma unroll
            for (int nt = 0; nt < 8; nt++)
                #pragma unroll
                for (int q = 0; q < 4; q++) acc[nt][q] *= SC_M;
        }
    }

    // epilogue: D = acc;  x = (hi + mid*2^-11) + lo*2^-22 read from gmem (exact)
    unsigned short pairs[2][8];
    #pragma unroll
    for (int h2 = 0; h2 < 2; h2++) {
        int px = (lane >> 2) + 8*h2;
        size_t gw = ((size_t)n*HWHW + (size_t)(h0 + wid)*WW + (w0 + px))*32 + (lane & 3);
        #pragma unroll
        for (int nt = 0; nt < 8; nt++) {
            unsigned wh = __ldg(xhi  + gw + nt*4);
            unsigned wm = __ldg(xmid + gw + nt*4);
            unsigned wl = __ldg(xlo  + gw + nt*4);
            unsigned pr = 0;
            #pragma unroll
            for (int j = 0; j < 2; j++) {
                int co = nt*8 + (lane & 3)*2 + j;
                float v = fmaf(acc[nt][2*h2 + j], sAc[co], sBc[co]);
                __half xh = __ushort_as_half((unsigned short)((wh >> (16*j)) & 0xFFFF));
                __half xm = __ushort_as_half((unsigned short)((wm >> (16*j)) & 0xFFFF));
                __half xl = __ushort_as_half((unsigned short)((wl >> (16*j)) & 0xFFFF));
                float xv = (__half2float(xh) + __half2float(xm) * SC_M)
                         + __half2float(xl) * SC_L;
                float r = qhtanh_f(v) + qhtanh_f(xv);
                pr |= qrelu_code(r) << (8*j);
            }
            pairs[h2][nt] = (unsigned short)pr;
        }
    }
    __syncthreads();
    unsigned short* stag = (unsigned short*)halo;
    #pragma unroll
    for (int h2 = 0; h2 < 2; h2++) {
        int px = (lane >> 2) + 8*h2;
        int pxl = wid*16 + px;
        #pragma unroll
        for (int nt = 0; nt < 8; nt++)
            stag[pxl*32 + nt*4 + (lane & 3)] = pairs[h2][nt];
    }
    __syncthreads();
    {
        int pxl = tid >> 1, half = tid & 1;
        int h = h0 + (pxl >> 4), w = w0 + (pxl & 15);
        const uint4* src = (const uint4*)((char*)halo + pxl*64 + half*32);
        uint4* dst = (uint4*)(outp + ((size_t)n*HWHW + (size_t)h*WW + w)*16 + half*8);
        dst[0] = src[0];
        dst[1] = src[1];
    }
}

// ================ IMMA int stages (EPI 0/1/3) ================
// halo pitch 20 u32 = 80B: ldmatrix rows at banks 20r mod 32 -> conflict-free.
// smem: sB uint2[4608] (36864B) | halo u32[180][20] (14400B) => 51264B, 3 CTAs/SM
#define HPITCH_I 20
template<int EPI>
__global__ __launch_bounds__(256, 3)
void conv3x3_imma(const unsigned* __restrict__ act_in, const uint2* __restrict__ bfrag,
                  const float* __restrict__ Acoef, const float* __restrict__ Bcoef,
                  const unsigned* __restrict__ e1, unsigned* __restrict__ outp) {
    extern __shared__ char dsm[];
    uint2* sBf = (uint2*)dsm;
    unsigned* halo = (unsigned*)(dsm + 36864);
    __shared__ float sAc[64], sBc[64];

    int tid = threadIdx.x;
    int wid = tid >> 5;
    int lane = tid & 31;
    int n  = blockIdx.z;
    int h0 = blockIdx.y * 8;
    int w0 = blockIdx.x * 16;

    if (tid < 64) { sAc[tid] = Acoef[tid]; sBc[tid] = Bcoef[tid]; }
    {
        const uint4* src = (const uint4*)bfrag;
        uint4* dst = (uint4*)sBf;
        #pragma unroll
        for (int i = 0; i < 9; i++) dst[tid + i*256] = src[tid + i*256];
    }
    const unsigned* inN = act_in + (size_t)n*HWHW*16;
    for (int e = tid; e < 2880; e += 256) {
        int r = e / 288, rr = e % 288, c = rr >> 4, q = rr & 15;
        int hh = h0 - 1 + r, ww = w0 - 1 + c;
        unsigned v = 0;
        if ((unsigned)hh < HH && (unsigned)ww < WW)
            v = inN[((size_t)hh*WW + ww)*16 + q];
        halo[(r*18 + c)*HPITCH_I + q] = v;
    }
    __syncthreads();

    unsigned haloAddr = smem_u32(halo);
    unsigned aBase = haloAddr + (unsigned)((wid*18 + (lane & 15))*80 + (lane >> 4)*16);

    int acc[8][4];
    #pragma unroll
    for (int nt = 0; nt < 8; nt++)
        #pragma unroll
        for (int q = 0; q < 4; q++) acc[nt][q] = 0;

    #pragma unroll 1
    for (int dy = 0; dy < 3; dy++)
    #pragma unroll
    for (int dx = 0; dx < 3; dx++) {
        unsigned rowOff = aBase + (unsigned)((dy*18 + dx)*80);
        #pragma unroll
        for (int c = 0; c < 2; c++) {
            unsigned a0, a1, a2, a3;
            ldsm_x4(a0, a1, a2, a3, rowOff + c*32);
            const uint2* bp = sBf + ((dy*3 + dx)*2 + c)*256 + lane;
            #pragma unroll
            for (int nt = 0; nt < 8; nt++) {
                uint2 b = bp[nt*32];
                mma_s8(acc[nt], a0, a1, a2, a3, b.x, b.y);
            }
        }
    }

    // epilogue -> u8 code pairs
    unsigned short pairs[2][8];
    int ctr_row = (wid + 1)*18;
    #pragma unroll
    for (int h2 = 0; h2 < 2; h2++) {
        int px = (lane >> 2) + 8*h2;
        int ctr = (ctr_row + px + 1)*HPITCH_I;
        size_t pixw = ((size_t)n*HWHW + (size_t)(h0 + wid)*WW + (w0 + px))*16;
        int wsel = (lane & 3) >> 1;
        int b0 = ((lane & 3) & 1)*2;
        #pragma unroll
        for (int nt = 0; nt < 8; nt++) {
            unsigned inw = halo[ctr + 2*nt + wsel];
            unsigned ew = 0;
            if (EPI == 1 || EPI == 3) ew = e1[pixw + 2*nt + wsel];
            unsigned pr = 0;
            #pragma unroll
            for (int j = 0; j < 2; j++) {
                int co = nt*8 + (lane & 3)*2 + j;
                float v = fmaf((float)acc[nt][2*h2 + j], sAc[co], sBc[co]);
                int byte = b0 + j;
                float in_val = (float)((inw >> (8*byte)) & 255u) * R_S;
                float r;
                if (EPI == 0) {
                    r = qhtanh_f(v) + qhtanh_f(in_val);
                } else if (EPI == 1) {
                    int ec = (int)(ew << (24 - 8*byte)) >> 24;
                    float tq = qhtanh_f(v) + (float)ec * HT_S;
                    r = qhtanh_f(tq) + qhtanh_f(in_val);
                } else {
                    float ev = (float)((ew >> (8*byte)) & 255u) * R_S;
                    float tq = qhtanh_f(v) + qhtanh_f(ev);
                    r = qhtanh_f(in_val) + qhtanh_f(tq);
                }
                pr |= qrelu_code(r) << (8*j);
            }
            pairs[h2][nt] = (unsigned short)pr;
        }
    }
    __syncthreads();                       // all halo reads done; reuse as staging
    unsigned short* stag = (unsigned short*)halo;
    #pragma unroll
    for (int h2 = 0; h2 < 2; h2++) {
        int px = (lane >> 2) + 8*h2;
        int pxl = wid*16 + px;
        #pragma unroll
        for (int nt = 0; nt < 8; nt++)
            stag[pxl*32 + nt*4 + (lane & 3)] = pairs[h2][nt];
    }
    __syncthreads();
    {
        int pxl = tid >> 1, half = tid & 1;
        int h = h0 + (pxl >> 4), w = w0 + (pxl & 15);
        const uint4* src = (const uint4*)((char*)halo + pxl*64 + half*32);
        uint4* dst = (uint4*)(outp + ((size_t)n*HWHW + (size_t)h*WW + w)*16 + half*8);
        dst[0] = src[0];
        dst[1] = src[1];
    }
}

// -------- final: u8 NHWC codes -> fp32 NCHW (out = code * R_S) --------
__global__ void out_expand_kernel(const unsigned* __restrict__ codes,
                                  float* __restrict__ out) {
    __shared__ unsigned st[64][17];
    int blk = blockIdx.x;             // 16*196
    int n = blk / 196;
    int pix0 = (blk % 196) * 64;
    int tid = threadIdx.x;
    #pragma unroll
    for (int i = 0; i < 4; i++) {
        int e = tid + i*256;
        int px = e >> 4, q = e & 15;
        st[px][q] = codes[((size_t)n*HWHW + pix0 + px)*16 + q];
    }
    __syncthreads();
    int c = tid >> 2, qq = tid & 3;
    float* dst = out + ((size_t)n*64 + c)*HWHW + pix0 + qq*16;
    #pragma unroll
    for (int i = 0; i < 16; i++) {
        unsigned w = st[qq*16 + i][c >> 2];
        dst[i] = (float)((w >> (8*(c & 3))) & 255u) * R_S;
    }
}

// -------------------- host launcher --------------------------------
extern "C" void kernel_launch(void* const* d_in, const int* in_sizes, int n_in,
                              void* d_out, int out_size) {
    const float* x      = (const float*)d_in[0];
    const float* conv_w = (const float*)d_in[1];
    const float* ds_w   = (const float*)d_in[2];
    const float* bng    = (const float*)d_in[3];
    const float* bnb    = (const float*)d_in[4];
    const float* bnm    = (const float*)d_in[5];
    const float* bnvv   = (const float*)d_in[6];
    float* out = (float*)d_out;

    unsigned *act1, *act2, *act3, *act4, *idq, *xhi, *xmid, *xlo;
    uint2 *bfi, *bfh;
    float *dsq, *wsc, *A, *B, *inv4, *bias4;
    cudaGetSymbolAddress((void**)&act1, g_act1);
    cudaGetSymbolAddress((void**)&act2, g_act2);
    cudaGetSymbolAddress((void**)&act3, g_act3);
    cudaGetSymbolAddress((void**)&act4, g_act4);
    cudaGetSymbolAddress((void**)&idq,  g_idq);
    cudaGetSymbolAddress((void**)&xhi,  g_xhi);
    cudaGetSymbolAddress((void**)&xmid, g_xmid);
    cudaGetSymbolAddress((void**)&xlo,  g_xlo);
    cudaGetSymbolAddress((void**)&bfi,  g_bfi);
    cudaGetSymbolAddress((void**)&bfh,  g_bfh);
    cudaGetSymbolAddress((void**)&dsq,  g_dsq);
    cudaGetSymbolAddress((void**)&wsc,  g_wsc);
    cudaGetSymbolAddress((void**)&A,    g_A);
    cudaGetSymbolAddress((void**)&B,    g_B);
    cudaGetSymbolAddress((void**)&inv4, g_bninv4);
    cudaGetSymbolAddress((void**)&bias4,g_bnbias4);

    const int SMEMI = 36864 + 14400;            // 51,264 -> 3 CTAs/SM
    const int SMEM0 = 73728 + 25920;            // 99,648 -> 2 CTAs/SM
    cudaFuncSetAttribute(conv3x3_hmma0,   cudaFuncAttributeMaxDynamicSharedMemorySize, SMEM0);
    cudaFuncSetAttribute(conv3x3_imma<0>, cudaFuncAttributeMaxDynamicSharedMemorySize, SMEMI);
    cudaFuncSetAttribute(conv3x3_imma<1>, cudaFuncAttributeMaxDynamicSharedMemorySize, SMEMI);
    cudaFuncSetAttribute(conv3x3_imma<3>, cudaFuncAttributeMaxDynamicSharedMemorySize, SMEMI);

    // launch #1: fused prep; #2: bn coefs; #3: conv1x1; #4: hmma0 (profiled)
    prep1_kernel<<<PREP1_GRID, 256>>>(conv_w, ds_w, x, wsc, bfi, bfh, dsq, xhi, xmid, xlo);
    prep2_kernel<<<1, 320>>>(bng, bnb, bnm, bnvv, wsc, A, B, inv4, bias4);
    conv1x1_kernel<<<784, 256>>>(x, dsq, inv4, bias4, idq);

    dim3 grid(7, 14, NN);   // 16w x 8h tiles
    conv3x3_hmma0<<<grid, 256, SMEM0>>>(xhi, xmid, xlo, bfh, A + 0*CC, B + 0*CC, act1);
    conv3x3_imma<1><<<grid, 256, SMEMI>>>(act1, bfi + 0*4608, A + 1*CC, B + 1*CC, idq,  act2);
    conv3x3_imma<0><<<grid, 256, SMEMI>>>(act2, bfi + 1*4608, A + 2*CC, B + 2*CC, nullptr, act3);
    conv3x3_imma<3><<<grid, 256, SMEMI>>>(act3, bfi + 2*4608, A + 3*CC, B + 3*CC, act2, act4);
    out_expand_kernel<<<16*196, 256>>>(act4, out);
}